// round 3
// baseline (speedup 1.0000x reference)
#include <cuda_runtime.h>
#include <math.h>

#define DIM 1024
#define INNER 1024
#define SEQ 2048
#define BATCH 4
#define HEADS 16
#define HEAD_DIM 64
#define ROWS (BATCH*SEQ)            // 8192
#define ATTN_SMEM (4*64*68*4)       // q_s,k_s,v_s,p_s tiles, padded rows

// Scratch (no runtime allocation allowed)
__device__ float g_xn[(size_t)ROWS * DIM];
__device__ float g_qkv[(size_t)ROWS * 3 * INNER];
__device__ float g_attn[(size_t)ROWS * INNER];

// ---------------------------------------------------------------------------
// LayerNorm: one block per row of 1024, 256 threads, float4 per thread
// ---------------------------------------------------------------------------
__global__ void ln_kernel(const float* __restrict__ x, const float* __restrict__ g,
                          const float* __restrict__ beta, float* __restrict__ out) {
    int row = blockIdx.x;
    int t = threadIdx.x;
    const float4* xr = (const float4*)(x + (size_t)row * DIM);
    float4 v = xr[t];
    float s  = v.x + v.y + v.z + v.w;
    float ss = v.x*v.x + v.y*v.y + v.z*v.z + v.w*v.w;
    #pragma unroll
    for (int o = 16; o; o >>= 1) {
        s  += __shfl_xor_sync(0xffffffffu, s,  o);
        ss += __shfl_xor_sync(0xffffffffu, ss, o);
    }
    __shared__ float sbuf[8], ssbuf[8];
    __shared__ float mu_s, rstd_s;
    if ((t & 31) == 0) { sbuf[t >> 5] = s; ssbuf[t >> 5] = ss; }
    __syncthreads();
    if (t == 0) {
        float st = 0.f, sst = 0.f;
        #pragma unroll
        for (int i = 0; i < 8; i++) { st += sbuf[i]; sst += ssbuf[i]; }
        float mu  = st * (1.0f / DIM);
        float var = sst * (1.0f / DIM) - mu * mu;
        mu_s = mu;
        rstd_s = rsqrtf(var + 1e-5f);
    }
    __syncthreads();
    float mu = mu_s, rstd = rstd_s;
    float4 gv = ((const float4*)g)[t];
    float4 bv = ((const float4*)beta)[t];
    float4 o4;
    o4.x = (v.x - mu) * rstd * gv.x + bv.x;
    o4.y = (v.y - mu) * rstd * gv.y + bv.y;
    o4.z = (v.z - mu) * rstd * gv.z + bv.z;
    o4.w = (v.w - mu) * rstd * gv.w + bv.w;
    ((float4*)(out + (size_t)row * DIM))[t] = o4;
}

// ---------------------------------------------------------------------------
// GEMM + bias: C[M,N] = A[M,K] @ B[K,N] + bias[N]
// 64x64 block tile, BK=16, 256 threads, 4x4 per thread
// ---------------------------------------------------------------------------
__global__ void gemm_bias_kernel(const float* __restrict__ A, const float* __restrict__ B,
                                 const float* __restrict__ bias, float* __restrict__ C,
                                 int M, int N, int K) {
    __shared__ float As[16][64];   // As[k][m]
    __shared__ float Bs[16][64];   // Bs[k][n]
    int t  = threadIdx.x;
    int tm = t >> 4;               // 0..15
    int tn = t & 15;               // 0..15
    int m0 = blockIdx.y << 6;
    int n0 = blockIdx.x << 6;

    int arow = t >> 2;             // 0..63
    int ak   = (t & 3) << 2;       // 0,4,8,12
    int bk   = t >> 4;             // 0..15
    int bn   = (t & 15) << 2;      // 0..60

    const float* Ap = A + (size_t)(m0 + arow) * K + ak;
    const float* Bp = B + (size_t)bk * N + n0 + bn;

    float acc[4][4] = {};

    for (int k0 = 0; k0 < K; k0 += 16) {
        float4 a = *(const float4*)(Ap + k0);
        float4 b = *(const float4*)(Bp + (size_t)k0 * N);
        As[ak + 0][arow] = a.x;
        As[ak + 1][arow] = a.y;
        As[ak + 2][arow] = a.z;
        As[ak + 3][arow] = a.w;
        *(float4*)&Bs[bk][bn] = b;
        __syncthreads();
        #pragma unroll
        for (int kk = 0; kk < 16; kk++) {
            float4 av = *(const float4*)&As[kk][tm << 2];
            float4 bv = *(const float4*)&Bs[kk][tn << 2];
            acc[0][0] += av.x * bv.x; acc[0][1] += av.x * bv.y; acc[0][2] += av.x * bv.z; acc[0][3] += av.x * bv.w;
            acc[1][0] += av.y * bv.x; acc[1][1] += av.y * bv.y; acc[1][2] += av.y * bv.z; acc[1][3] += av.y * bv.w;
            acc[2][0] += av.z * bv.x; acc[2][1] += av.z * bv.y; acc[2][2] += av.z * bv.z; acc[2][3] += av.z * bv.w;
            acc[3][0] += av.w * bv.x; acc[3][1] += av.w * bv.y; acc[3][2] += av.w * bv.z; acc[3][3] += av.w * bv.w;
        }
        __syncthreads();
    }

    float4 bb = *(const float4*)&bias[n0 + (tn << 2)];
    #pragma unroll
    for (int i = 0; i < 4; i++) {
        float4 o;
        o.x = acc[i][0] + bb.x;
        o.y = acc[i][1] + bb.y;
        o.z = acc[i][2] + bb.z;
        o.w = acc[i][3] + bb.w;
        *(float4*)&C[(size_t)(m0 + (tm << 2) + i) * N + n0 + (tn << 2)] = o;
    }
}

// ---------------------------------------------------------------------------
// Flash attention: grid (b*h = 64, qtile = 32), 256 threads.
// 64-query tile, iterate 32 kv tiles of 64. Online softmax.
// Each thread owns a 4x4 micro-tile of S and of O.
// Writes directly into [b, s, h*64+d] layout (fuses the transpose).
// ---------------------------------------------------------------------------
__global__ void attn_kernel(const float* __restrict__ qkv, float* __restrict__ out) {
    extern __shared__ float sh[];
    float* q_s = sh;                 // [64][68]
    float* k_s = q_s + 64 * 68;
    float* v_s = k_s + 64 * 68;
    float* p_s = v_s + 64 * 68;

    int bh = blockIdx.x;
    int b  = bh >> 4;
    int h  = bh & 15;
    int qt = blockIdx.y;
    int t  = threadIdx.x;
    int tm = t >> 4;                 // 0..15 (row group)
    int tn = t & 15;                 // 0..15 (col group)
    const float scale = 0.125f;      // 1/sqrt(64)

    int lr = t >> 2;                 // 0..63 loader row
    int lc = (t & 3) << 4;           // 0,16,32,48 loader col

    // Load Q tile
    {
        size_t qbase = ((size_t)(b * SEQ + (qt << 6) + lr)) * (3 * INNER) + h * HEAD_DIM + lc;
        #pragma unroll
        for (int q4 = 0; q4 < 4; q4++)
            *(float4*)&q_s[lr * 68 + lc + (q4 << 2)] = *(const float4*)(qkv + qbase + (q4 << 2));
    }

    float o[4][4] = {};
    float m_i[4], l_i[4];
    #pragma unroll
    for (int i = 0; i < 4; i++) { m_i[i] = -1e30f; l_i[i] = 0.f; }

    for (int kt = 0; kt < SEQ / 64; kt++) {
        __syncthreads();   // previous O-update consumers of v_s/p_s done
        // Load K and V tiles
        size_t kbase = ((size_t)(b * SEQ + (kt << 6) + lr)) * (3 * INNER) + INNER + h * HEAD_DIM + lc;
        #pragma unroll
        for (int q4 = 0; q4 < 4; q4++) {
            *(float4*)&k_s[lr * 68 + lc + (q4 << 2)] = *(const float4*)(qkv + kbase + (q4 << 2));
            *(float4*)&v_s[lr * 68 + lc + (q4 << 2)] = *(const float4*)(qkv + kbase + INNER + (q4 << 2));
        }
        __syncthreads();

        // S = Q K^T (4x4 per thread)
        float s[4][4] = {};
        #pragma unroll
        for (int d = 0; d < HEAD_DIM; d += 4) {
            float4 qa[4], kb[4];
            #pragma unroll
            for (int i = 0; i < 4; i++) qa[i] = *(const float4*)&q_s[((tm << 2) + i) * 68 + d];
            #pragma unroll
            for (int j = 0; j < 4; j++) kb[j] = *(const float4*)&k_s[((tn << 2) + j) * 68 + d];
            #pragma unroll
            for (int i = 0; i < 4; i++)
                #pragma unroll
                for (int j = 0; j < 4; j++)
                    s[i][j] += qa[i].x * kb[j].x + qa[i].y * kb[j].y
                             + qa[i].z * kb[j].z + qa[i].w * kb[j].w;
        }

        // Online softmax per row (row stats shared across the 16 tn-threads,
        // which are 16 contiguous lanes of the same warp)
        #pragma unroll
        for (int i = 0; i < 4; i++) {
            float mt = -1e30f;
            #pragma unroll
            for (int j = 0; j < 4; j++) { s[i][j] *= scale; mt = fmaxf(mt, s[i][j]); }
            #pragma unroll
            for (int o2 = 8; o2; o2 >>= 1) mt = fmaxf(mt, __shfl_xor_sync(0xffffffffu, mt, o2));
            float m_new = fmaxf(m_i[i], mt);
            float corr = __expf(m_i[i] - m_new);
            float ls = 0.f;
            #pragma unroll
            for (int j = 0; j < 4; j++) { s[i][j] = __expf(s[i][j] - m_new); ls += s[i][j]; }
            #pragma unroll
            for (int o2 = 8; o2; o2 >>= 1) ls += __shfl_xor_sync(0xffffffffu, ls, o2);
            l_i[i] = l_i[i] * corr + ls;
            m_i[i] = m_new;
            #pragma unroll
            for (int j = 0; j < 4; j++) o[i][j] *= corr;
            *(float4*)&p_s[((tm << 2) + i) * 68 + (tn << 2)] =
                make_float4(s[i][0], s[i][1], s[i][2], s[i][3]);
        }
        __syncthreads();

        // O += P @ V  (4x4 per thread, full 64-deep k loop)
        #pragma unroll 4
        for (int k = 0; k < 64; k++) {
            float4 vv = *(const float4*)&v_s[k * 68 + (tn << 2)];
            float p0 = p_s[((tm << 2) + 0) * 68 + k];
            float p1 = p_s[((tm << 2) + 1) * 68 + k];
            float p2 = p_s[((tm << 2) + 2) * 68 + k];
            float p3 = p_s[((tm << 2) + 3) * 68 + k];
            o[0][0] += p0 * vv.x; o[0][1] += p0 * vv.y; o[0][2] += p0 * vv.z; o[0][3] += p0 * vv.w;
            o[1][0] += p1 * vv.x; o[1][1] += p1 * vv.y; o[1][2] += p1 * vv.z; o[1][3] += p1 * vv.w;
            o[2][0] += p2 * vv.x; o[2][1] += p2 * vv.y; o[2][2] += p2 * vv.z; o[2][3] += p2 * vv.w;
            o[3][0] += p3 * vv.x; o[3][1] += p3 * vv.y; o[3][2] += p3 * vv.z; o[3][3] += p3 * vv.w;
        }
    }

    // Finalize: divide by l, write to [b, s, h*64 + d] (fused transpose)
    #pragma unroll
    for (int i = 0; i < 4; i++) {
        float inv = 1.0f / l_i[i];
        size_t obase = ((size_t)(b * SEQ + (qt << 6) + (tm << 2) + i)) * INNER
                     + h * HEAD_DIM + (tn << 2);
        float4 ov = make_float4(o[i][0] * inv, o[i][1] * inv, o[i][2] * inv, o[i][3] * inv);
        *(float4*)(out + obase) = ov;
    }
}

// ---------------------------------------------------------------------------
extern "C" void kernel_launch(void* const* d_in, const int* in_sizes, int n_in,
                              void* d_out, int out_size) {
    const float* x     = (const float*)d_in[0];
    const float* ln_g  = (const float*)d_in[1];
    const float* ln_b  = (const float*)d_in[2];
    const float* w_qkv = (const float*)d_in[3];
    const float* b_qkv = (const float*)d_in[4];
    const float* w_out = (const float*)d_in[5];
    const float* b_out = (const float*)d_in[6];
    float* out = (float*)d_out;

    float *xn, *qkv, *attn;
    cudaGetSymbolAddress((void**)&xn,   g_xn);
    cudaGetSymbolAddress((void**)&qkv,  g_qkv);
    cudaGetSymbolAddress((void**)&attn, g_attn);

    cudaFuncSetAttribute(attn_kernel, cudaFuncAttributeMaxDynamicSharedMemorySize, ATTN_SMEM);

    // 1) LayerNorm
    ln_kernel<<<ROWS, 256>>>(x, ln_g, ln_b, xn);
    // 2) QKV projection: [8192,1024] @ [1024,3072] + bias
    gemm_bias_kernel<<<dim3((3 * INNER) / 64, ROWS / 64), 256>>>(xn, w_qkv, b_qkv, qkv,
                                                                 ROWS, 3 * INNER, DIM);
    // 3) Attention (writes [b,s,inner] directly)
    attn_kernel<<<dim3(BATCH * HEADS, SEQ / 64), 256, ATTN_SMEM>>>(qkv, attn);
    // 4) Output projection: [8192,1024] @ [1024,1024] + bias
    gemm_bias_kernel<<<dim3(DIM / 64, ROWS / 64), 256>>>(attn, w_out, b_out, out,
                                                         ROWS, DIM, INNER);
}

// round 4
// speedup vs baseline: 1.5534x; 1.5534x over previous
#include <cuda_runtime.h>
#include <math.h>

#define DIM 1024
#define INNER 1024
#define SEQ 2048
#define BATCH 4
#define HEADS 16
#define HEAD_DIM 64
#define ROWS (BATCH*SEQ)            // 8192

// attention smem: q[128][68] + kT[64][68] + v[64][68] + p[128][68]
#define ATTN_SMEM ((128*68 + 64*68 + 64*68 + 128*68) * 4)

// Scratch (no runtime allocation allowed)
__device__ float g_xn[(size_t)ROWS * DIM];
__device__ float g_qkv[(size_t)ROWS * 3 * INNER];
__device__ float g_attn[(size_t)ROWS * INNER];

// ---------------------------------------------------------------------------
// LayerNorm: one block per row of 1024, 256 threads, float4 per thread
// ---------------------------------------------------------------------------
__global__ void ln_kernel(const float* __restrict__ x, const float* __restrict__ g,
                          const float* __restrict__ beta, float* __restrict__ out) {
    int row = blockIdx.x;
    int t = threadIdx.x;
    const float4* xr = (const float4*)(x + (size_t)row * DIM);
    float4 v = xr[t];
    float s  = v.x + v.y + v.z + v.w;
    float ss = v.x*v.x + v.y*v.y + v.z*v.z + v.w*v.w;
    #pragma unroll
    for (int o = 16; o; o >>= 1) {
        s  += __shfl_xor_sync(0xffffffffu, s,  o);
        ss += __shfl_xor_sync(0xffffffffu, ss, o);
    }
    __shared__ float sbuf[8], ssbuf[8];
    __shared__ float mu_s, rstd_s;
    if ((t & 31) == 0) { sbuf[t >> 5] = s; ssbuf[t >> 5] = ss; }
    __syncthreads();
    if (t == 0) {
        float st = 0.f, sst = 0.f;
        #pragma unroll
        for (int i = 0; i < 8; i++) { st += sbuf[i]; sst += ssbuf[i]; }
        float mu  = st * (1.0f / DIM);
        float var = sst * (1.0f / DIM) - mu * mu;
        mu_s = mu;
        rstd_s = rsqrtf(var + 1e-5f);
    }
    __syncthreads();
    float mu = mu_s, rstd = rstd_s;
    float4 gv = ((const float4*)g)[t];
    float4 bv = ((const float4*)beta)[t];
    float4 o4;
    o4.x = (v.x - mu) * rstd * gv.x + bv.x;
    o4.y = (v.y - mu) * rstd * gv.y + bv.y;
    o4.z = (v.z - mu) * rstd * gv.z + bv.z;
    o4.w = (v.w - mu) * rstd * gv.w + bv.w;
    ((float4*)(out + (size_t)row * DIM))[t] = o4;
}

// ---------------------------------------------------------------------------
// GEMM + bias: C[M,N] = A[M,K] @ B[K,N] + bias[N]
// 128x128 block tile, BK=8, 256 threads, 8x8 micro tile, double-buffered smem
// ---------------------------------------------------------------------------
__global__ __launch_bounds__(256, 2)
void gemm_bias_kernel(const float* __restrict__ A, const float* __restrict__ B,
                      const float* __restrict__ bias, float* __restrict__ C,
                      int M, int N, int K) {
    __shared__ float As[2][8][132];   // As[buf][k][m]
    __shared__ float Bs[2][8][132];   // Bs[buf][k][n]
    int t  = threadIdx.x;
    int m0 = blockIdx.y << 7;
    int n0 = blockIdx.x << 7;
    int tm = (t >> 4) << 3;           // 0..120 step 8
    int tn = (t & 15) << 3;           // 0..120 step 8

    int am = t >> 1;                  // 0..127
    int ak = (t & 1) << 2;            // 0 or 4
    int bk = t >> 5;                  // 0..7
    int bn = (t & 31) << 2;           // 0..124

    const float* Ap = A + (size_t)(m0 + am) * K + ak;
    const float* Bp = B + (size_t)bk * N + n0 + bn;

    float acc[8][8] = {};
    float4 a_reg, b_reg;

    // prologue
    a_reg = *(const float4*)Ap;
    b_reg = *(const float4*)Bp;
    As[0][ak + 0][am] = a_reg.x; As[0][ak + 1][am] = a_reg.y;
    As[0][ak + 2][am] = a_reg.z; As[0][ak + 3][am] = a_reg.w;
    *(float4*)&Bs[0][bk][bn] = b_reg;
    __syncthreads();

    int nk = K >> 3;
    for (int k0 = 0; k0 < nk; k0++) {
        int cur = k0 & 1;
        if (k0 + 1 < nk) {
            a_reg = *(const float4*)(Ap + ((k0 + 1) << 3));
            b_reg = *(const float4*)(Bp + (size_t)((k0 + 1) << 3) * N);
        }
        #pragma unroll
        for (int kk = 0; kk < 8; kk++) {
            float4 a0 = *(const float4*)&As[cur][kk][tm];
            float4 a1 = *(const float4*)&As[cur][kk][tm + 4];
            float4 b0 = *(const float4*)&Bs[cur][kk][tn];
            float4 b1 = *(const float4*)&Bs[cur][kk][tn + 4];
            float av[8] = {a0.x, a0.y, a0.z, a0.w, a1.x, a1.y, a1.z, a1.w};
            float bv[8] = {b0.x, b0.y, b0.z, b0.w, b1.x, b1.y, b1.z, b1.w};
            #pragma unroll
            for (int i = 0; i < 8; i++)
                #pragma unroll
                for (int j = 0; j < 8; j++)
                    acc[i][j] += av[i] * bv[j];
        }
        if (k0 + 1 < nk) {
            int nxt = cur ^ 1;
            As[nxt][ak + 0][am] = a_reg.x; As[nxt][ak + 1][am] = a_reg.y;
            As[nxt][ak + 2][am] = a_reg.z; As[nxt][ak + 3][am] = a_reg.w;
            *(float4*)&Bs[nxt][bk][bn] = b_reg;
        }
        __syncthreads();
    }

    float4 bb0 = *(const float4*)&bias[n0 + tn];
    float4 bb1 = *(const float4*)&bias[n0 + tn + 4];
    #pragma unroll
    for (int i = 0; i < 8; i++) {
        float* Cp = C + (size_t)(m0 + tm + i) * N + n0 + tn;
        float4 o0 = make_float4(acc[i][0] + bb0.x, acc[i][1] + bb0.y,
                                acc[i][2] + bb0.z, acc[i][3] + bb0.w);
        float4 o1 = make_float4(acc[i][4] + bb1.x, acc[i][5] + bb1.y,
                                acc[i][6] + bb1.z, acc[i][7] + bb1.w);
        *(float4*)Cp = o0;
        *(float4*)(Cp + 4) = o1;
    }
}

// ---------------------------------------------------------------------------
// Flash attention: grid (b*h = 64, qtile = 16), 256 threads.
// 128-query tile x 64-kv tile. 8x4 micro tiles for S and O.
// K stored transposed in smem ([d][k]) for conflict-free column access.
// P stored [q][k]: float4 writes (conflict-free), broadcast scalar reads.
// ---------------------------------------------------------------------------
__global__ __launch_bounds__(256, 2)
void attn_kernel(const float* __restrict__ qkv, float* __restrict__ out) {
    extern __shared__ float sh[];
    float* q_s = sh;                   // [128][68]
    float* kt_s = q_s + 128 * 68;      // [64][68]  transposed: kt_s[d][k]
    float* v_s  = kt_s + 64 * 68;      // [64][68]
    float* p_s  = v_s + 64 * 68;       // [128][68]

    int b  = blockIdx.x >> 4;
    int h  = blockIdx.x & 15;
    int q0 = blockIdx.y << 7;
    int t  = threadIdx.x;
    int tm = (t >> 4) << 3;            // q-rows tm..tm+7 (0..120)
    int tn = (t & 15) << 2;            // kv/d-cols tn..tn+3 (0..60)
    const float scale = 0.125f;        // 1/sqrt(64)

    // Load Q tile: 128 rows x 64 cols = 2048 float4, 8 per thread
    #pragma unroll
    for (int it = 0; it < 8; it++) {
        int idx = t + (it << 8);
        int r = idx >> 4, c = (idx & 15) << 2;
        size_t g = ((size_t)(b * SEQ + q0 + r)) * 3072 + h * HEAD_DIM + c;
        *(float4*)&q_s[r * 68 + c] = *(const float4*)(qkv + g);
    }

    float o[8][4] = {};
    float m_i[8], l_i[8];
    #pragma unroll
    for (int i = 0; i < 8; i++) { m_i[i] = -1e30f; l_i[i] = 0.f; }

    for (int kt = 0; kt < SEQ / 64; kt++) {
        __syncthreads();   // prev iteration's PV reads of v_s/p_s & S reads of kt_s done
        // Load K (transposed into smem) and V: 64x64 each, 4 float4 per thread
        #pragma unroll
        for (int it = 0; it < 4; it++) {
            int idx = t + (it << 8);
            int r = idx >> 4, c = (idx & 15) << 2;
            size_t g = ((size_t)(b * SEQ + (kt << 6) + r)) * 3072 + INNER + h * HEAD_DIM + c;
            float4 kv4 = *(const float4*)(qkv + g);
            kt_s[(c + 0) * 68 + r] = kv4.x;
            kt_s[(c + 1) * 68 + r] = kv4.y;
            kt_s[(c + 2) * 68 + r] = kv4.z;
            kt_s[(c + 3) * 68 + r] = kv4.w;
            *(float4*)&v_s[r * 68 + c] = *(const float4*)(qkv + g + INNER);
        }
        __syncthreads();

        // S = Q K^T : 8x4 per thread
        float s[8][4] = {};
        #pragma unroll
        for (int d = 0; d < HEAD_DIM; d += 4) {
            float4 kb0 = *(const float4*)&kt_s[(d + 0) * 68 + tn];
            float4 kb1 = *(const float4*)&kt_s[(d + 1) * 68 + tn];
            float4 kb2 = *(const float4*)&kt_s[(d + 2) * 68 + tn];
            float4 kb3 = *(const float4*)&kt_s[(d + 3) * 68 + tn];
            #pragma unroll
            for (int i = 0; i < 8; i++) {
                float4 qa = *(const float4*)&q_s[(tm + i) * 68 + d];
                s[i][0] += qa.x * kb0.x + qa.y * kb1.x + qa.z * kb2.x + qa.w * kb3.x;
                s[i][1] += qa.x * kb0.y + qa.y * kb1.y + qa.z * kb2.y + qa.w * kb3.y;
                s[i][2] += qa.x * kb0.z + qa.y * kb1.z + qa.z * kb2.z + qa.w * kb3.z;
                s[i][3] += qa.x * kb0.w + qa.y * kb1.w + qa.z * kb2.w + qa.w * kb3.w;
            }
        }

        // Online softmax per row (16 tn-lanes of the same warp share a row)
        #pragma unroll
        for (int i = 0; i < 8; i++) {
            float mt = -1e30f;
            #pragma unroll
            for (int j = 0; j < 4; j++) { s[i][j] *= scale; mt = fmaxf(mt, s[i][j]); }
            #pragma unroll
            for (int o2 = 8; o2; o2 >>= 1) mt = fmaxf(mt, __shfl_xor_sync(0xffffffffu, mt, o2));
            float m_new = fmaxf(m_i[i], mt);
            float corr = __expf(m_i[i] - m_new);
            float ls = 0.f;
            #pragma unroll
            for (int j = 0; j < 4; j++) { s[i][j] = __expf(s[i][j] - m_new); ls += s[i][j]; }
            #pragma unroll
            for (int o2 = 8; o2; o2 >>= 1) ls += __shfl_xor_sync(0xffffffffu, ls, o2);
            l_i[i] = l_i[i] * corr + ls;
            m_i[i] = m_new;
            #pragma unroll
            for (int j = 0; j < 4; j++) o[i][j] *= corr;
            *(float4*)&p_s[(tm + i) * 68 + tn] =
                make_float4(s[i][0], s[i][1], s[i][2], s[i][3]);
        }
        __syncthreads();

        // O += P @ V : 8x4 per thread
        #pragma unroll 4
        for (int k = 0; k < 64; k++) {
            float4 vv = *(const float4*)&v_s[k * 68 + tn];
            float p0 = p_s[(tm + 0) * 68 + k];
            float p1 = p_s[(tm + 1) * 68 + k];
            float p2 = p_s[(tm + 2) * 68 + k];
            float p3 = p_s[(tm + 3) * 68 + k];
            float p4 = p_s[(tm + 4) * 68 + k];
            float p5 = p_s[(tm + 5) * 68 + k];
            float p6 = p_s[(tm + 6) * 68 + k];
            float p7 = p_s[(tm + 7) * 68 + k];
            o[0][0] += p0 * vv.x; o[0][1] += p0 * vv.y; o[0][2] += p0 * vv.z; o[0][3] += p0 * vv.w;
            o[1][0] += p1 * vv.x; o[1][1] += p1 * vv.y; o[1][2] += p1 * vv.z; o[1][3] += p1 * vv.w;
            o[2][0] += p2 * vv.x; o[2][1] += p2 * vv.y; o[2][2] += p2 * vv.z; o[2][3] += p2 * vv.w;
            o[3][0] += p3 * vv.x; o[3][1] += p3 * vv.y; o[3][2] += p3 * vv.z; o[3][3] += p3 * vv.w;
            o[4][0] += p4 * vv.x; o[4][1] += p4 * vv.y; o[4][2] += p4 * vv.z; o[4][3] += p4 * vv.w;
            o[5][0] += p5 * vv.x; o[5][1] += p5 * vv.y; o[5][2] += p5 * vv.z; o[5][3] += p5 * vv.w;
            o[6][0] += p6 * vv.x; o[6][1] += p6 * vv.y; o[6][2] += p6 * vv.z; o[6][3] += p6 * vv.w;
            o[7][0] += p7 * vv.x; o[7][1] += p7 * vv.y; o[7][2] += p7 * vv.z; o[7][3] += p7 * vv.w;
        }
    }

    // Finalize: divide by l, write to [b, s, h*64 + d] (fused transpose)
    #pragma unroll
    for (int i = 0; i < 8; i++) {
        float inv = 1.0f / l_i[i];
        size_t obase = ((size_t)(b * SEQ + q0 + tm + i)) * INNER + h * HEAD_DIM + tn;
        float4 ov = make_float4(o[i][0] * inv, o[i][1] * inv, o[i][2] * inv, o[i][3] * inv);
        *(float4*)(out + obase) = ov;
    }
}

// ---------------------------------------------------------------------------
extern "C" void kernel_launch(void* const* d_in, const int* in_sizes, int n_in,
                              void* d_out, int out_size) {
    const float* x     = (const float*)d_in[0];
    const float* ln_g  = (const float*)d_in[1];
    const float* ln_b  = (const float*)d_in[2];
    const float* w_qkv = (const float*)d_in[3];
    const float* b_qkv = (const float*)d_in[4];
    const float* w_out = (const float*)d_in[5];
    const float* b_out = (const float*)d_in[6];
    float* out = (float*)d_out;

    float *xn, *qkv, *attn;
    cudaGetSymbolAddress((void**)&xn,   g_xn);
    cudaGetSymbolAddress((void**)&qkv,  g_qkv);
    cudaGetSymbolAddress((void**)&attn, g_attn);

    cudaFuncSetAttribute(attn_kernel, cudaFuncAttributeMaxDynamicSharedMemorySize, ATTN_SMEM);

    // 1) LayerNorm
    ln_kernel<<<ROWS, 256>>>(x, ln_g, ln_b, xn);
    // 2) QKV projection: [8192,1024] @ [1024,3072] + bias
    gemm_bias_kernel<<<dim3((3 * INNER) / 128, ROWS / 128), 256>>>(xn, w_qkv, b_qkv, qkv,
                                                                   ROWS, 3 * INNER, DIM);
    // 3) Attention (writes [b,s,inner] directly)
    attn_kernel<<<dim3(BATCH * HEADS, SEQ / 128), 256, ATTN_SMEM>>>(qkv, attn);
    // 4) Output projection: [8192,1024] @ [1024,1024] + bias
    gemm_bias_kernel<<<dim3(DIM / 128, ROWS / 128), 256>>>(attn, w_out, b_out, out,
                                                           ROWS, DIM, INNER);
}

// round 5
// speedup vs baseline: 2.2897x; 1.4739x over previous
#include <cuda_runtime.h>
#include <math.h>
#include <stdint.h>

#define DIM 1024
#define INNER 1024
#define SEQ 2048
#define BATCH 4
#define HEADS 16
#define HEAD_DIM 64
#define ROWS (BATCH*SEQ)            // 8192

// attention smem: q[128][68] + kT[64][68] + v[64][68] + p[128][68]
#define ATTN_SMEM ((128*68 + 64*68 + 64*68 + 128*68) * 4)

// GEMM smem: As[2][128][36] + Bs[2][32][136] floats
#define GEMM_SMEM ((2*128*36 + 2*32*136) * 4)

// Scratch (no runtime allocation allowed)
__device__ float g_xn[(size_t)ROWS * DIM];
__device__ float g_qkv[(size_t)ROWS * 3 * INNER];
__device__ float g_attn[(size_t)ROWS * INNER];
__device__ float g_wqkv_t[(size_t)DIM * 3 * INNER];
__device__ float g_wout_t[(size_t)INNER * DIM];

__device__ __forceinline__ float tf32r(float x) {
    uint32_t u;
    asm("cvt.rna.tf32.f32 %0, %1;" : "=r"(u) : "f"(x));
    return __uint_as_float(u);
}

// ---------------------------------------------------------------------------
// Elementwise tf32 rounding (for weights), float4 per thread
// ---------------------------------------------------------------------------
__global__ void tf32_cvt_kernel(const float* __restrict__ in, float* __restrict__ out, int n4) {
    int i = blockIdx.x * 256 + threadIdx.x;
    if (i < n4) {
        float4 v = ((const float4*)in)[i];
        v.x = tf32r(v.x); v.y = tf32r(v.y); v.z = tf32r(v.z); v.w = tf32r(v.w);
        ((float4*)out)[i] = v;
    }
}

// ---------------------------------------------------------------------------
// LayerNorm: one block per row of 1024, 256 threads. Output rounded to tf32
// (it is consumed only as the A operand of the tf32 QKV GEMM).
// ---------------------------------------------------------------------------
__global__ void ln_kernel(const float* __restrict__ x, const float* __restrict__ g,
                          const float* __restrict__ beta, float* __restrict__ out) {
    int row = blockIdx.x;
    int t = threadIdx.x;
    const float4* xr = (const float4*)(x + (size_t)row * DIM);
    float4 v = xr[t];
    float s  = v.x + v.y + v.z + v.w;
    float ss = v.x*v.x + v.y*v.y + v.z*v.z + v.w*v.w;
    #pragma unroll
    for (int o = 16; o; o >>= 1) {
        s  += __shfl_xor_sync(0xffffffffu, s,  o);
        ss += __shfl_xor_sync(0xffffffffu, ss, o);
    }
    __shared__ float sbuf[8], ssbuf[8];
    __shared__ float mu_s, rstd_s;
    if ((t & 31) == 0) { sbuf[t >> 5] = s; ssbuf[t >> 5] = ss; }
    __syncthreads();
    if (t == 0) {
        float st = 0.f, sst = 0.f;
        #pragma unroll
        for (int i = 0; i < 8; i++) { st += sbuf[i]; sst += ssbuf[i]; }
        float mu  = st * (1.0f / DIM);
        float var = sst * (1.0f / DIM) - mu * mu;
        mu_s = mu;
        rstd_s = rsqrtf(var + 1e-5f);
    }
    __syncthreads();
    float mu = mu_s, rstd = rstd_s;
    float4 gv = ((const float4*)g)[t];
    float4 bv = ((const float4*)beta)[t];
    float4 o4;
    o4.x = tf32r((v.x - mu) * rstd * gv.x + bv.x);
    o4.y = tf32r((v.y - mu) * rstd * gv.y + bv.y);
    o4.z = tf32r((v.z - mu) * rstd * gv.z + bv.z);
    o4.w = tf32r((v.w - mu) * rstd * gv.w + bv.w);
    ((float4*)(out + (size_t)row * DIM))[t] = o4;
}

// ---------------------------------------------------------------------------
// tf32 tensor-core GEMM + bias: C[M,N] = A[M,K] @ B[K,N] + bias[N]
// A, B must be pre-rounded to tf32 (RNA). 128x128x32 tile, 256 threads,
// warp grid 2x4 (warp tile 64x32), mma.m16n8k8, cp.async double buffer.
// ---------------------------------------------------------------------------
#define CP_ASYNC16(dst, src) \
    asm volatile("cp.async.ca.shared.global [%0], [%1], 16;" :: "r"(dst), "l"(src))

__global__ __launch_bounds__(256, 2)
void gemm_tf32_kernel(const float* __restrict__ A, const float* __restrict__ B,
                      const float* __restrict__ bias, float* __restrict__ C,
                      int M, int N, int K) {
    extern __shared__ float sm[];
    float* As = sm;                       // [2][128][36]
    float* Bs = sm + 2 * 128 * 36;        // [2][32][136]

    int t = threadIdx.x;
    int warp = t >> 5, lane = t & 31;
    int warp_m = warp >> 2;               // 0..1
    int warp_n = warp & 3;                // 0..3
    int qr = lane >> 2;                   // 0..7
    int qc = lane & 3;                    // 0..3
    int m0 = blockIdx.y << 7;
    int n0 = blockIdx.x << 7;
    int mb = warp_m << 6;                 // warp m offset in tile
    int nb = warp_n << 5;                 // warp n offset in tile

    // global->smem load mapping (4 float4 per thread each for A and B)
    int a_m  = t >> 1;                    // handled via idx below
    (void)a_m;

    float acc[4][4][4] = {};

    // prologue: issue buffer 0
    {
        #pragma unroll
        for (int j = 0; j < 4; j++) {
            int idx = t + (j << 8);
            int m = idx >> 3, kc = (idx & 7) << 2;
            uint32_t dst = (uint32_t)__cvta_generic_to_shared(&As[m * 36 + kc]);
            CP_ASYNC16(dst, A + (size_t)(m0 + m) * K + kc);
        }
        #pragma unroll
        for (int j = 0; j < 4; j++) {
            int idx = t + (j << 8);
            int r = idx >> 5, c = (idx & 31) << 2;
            uint32_t dst = (uint32_t)__cvta_generic_to_shared(&Bs[r * 136 + c]);
            CP_ASYNC16(dst, B + (size_t)r * N + n0 + c);
        }
        asm volatile("cp.async.commit_group;");
    }

    int nk = K >> 5;                      // K/32 tiles
    for (int k0 = 0; k0 < nk; k0++) {
        asm volatile("cp.async.wait_group 0;");
        __syncthreads();
        int cur = k0 & 1;
        if (k0 + 1 < nk) {
            int nxt = cur ^ 1;
            int kbase = (k0 + 1) << 5;
            float* Asn = As + nxt * 128 * 36;
            float* Bsn = Bs + nxt * 32 * 136;
            #pragma unroll
            for (int j = 0; j < 4; j++) {
                int idx = t + (j << 8);
                int m = idx >> 3, kc = (idx & 7) << 2;
                uint32_t dst = (uint32_t)__cvta_generic_to_shared(&Asn[m * 36 + kc]);
                CP_ASYNC16(dst, A + (size_t)(m0 + m) * K + kbase + kc);
            }
            #pragma unroll
            for (int j = 0; j < 4; j++) {
                int idx = t + (j << 8);
                int r = idx >> 5, c = (idx & 31) << 2;
                uint32_t dst = (uint32_t)__cvta_generic_to_shared(&Bsn[r * 136 + c]);
                CP_ASYNC16(dst, B + (size_t)(kbase + r) * N + n0 + c);
            }
            asm volatile("cp.async.commit_group;");
        }

        const float* Ac = As + cur * 128 * 36;
        const float* Bc = Bs + cur * 32 * 136;

        #pragma unroll
        for (int ks = 0; ks < 4; ks++) {
            int k8 = ks << 3;
            uint32_t af[4][4], bf[4][2];
            #pragma unroll
            for (int mt = 0; mt < 4; mt++) {
                const float* ap = Ac + (mb + (mt << 4) + qr) * 36 + k8 + qc;
                af[mt][0] = __float_as_uint(ap[0]);
                af[mt][1] = __float_as_uint(ap[8 * 36]);
                af[mt][2] = __float_as_uint(ap[4]);
                af[mt][3] = __float_as_uint(ap[8 * 36 + 4]);
            }
            #pragma unroll
            for (int nt = 0; nt < 4; nt++) {
                const float* bp = Bc + (k8 + qc) * 136 + nb + (nt << 3) + qr;
                bf[nt][0] = __float_as_uint(bp[0]);
                bf[nt][1] = __float_as_uint(bp[4 * 136]);
            }
            #pragma unroll
            for (int mt = 0; mt < 4; mt++)
                #pragma unroll
                for (int nt = 0; nt < 4; nt++) {
                    asm volatile(
                        "mma.sync.aligned.m16n8k8.row.col.f32.tf32.tf32.f32 "
                        "{%0,%1,%2,%3}, {%4,%5,%6,%7}, {%8,%9}, {%0,%1,%2,%3};"
                        : "+f"(acc[mt][nt][0]), "+f"(acc[mt][nt][1]),
                          "+f"(acc[mt][nt][2]), "+f"(acc[mt][nt][3])
                        : "r"(af[mt][0]), "r"(af[mt][1]), "r"(af[mt][2]), "r"(af[mt][3]),
                          "r"(bf[nt][0]), "r"(bf[nt][1]));
                }
        }
        __syncthreads();
    }

    // epilogue: bias add + store (float2 per fragment row)
    #pragma unroll
    for (int nt = 0; nt < 4; nt++) {
        int col = n0 + nb + (nt << 3) + (qc << 1);
        float2 bb = *(const float2*)&bias[col];
        #pragma unroll
        for (int mt = 0; mt < 4; mt++) {
            int row = m0 + mb + (mt << 4) + qr;
            float2 v0 = make_float2(acc[mt][nt][0] + bb.x, acc[mt][nt][1] + bb.y);
            float2 v1 = make_float2(acc[mt][nt][2] + bb.x, acc[mt][nt][3] + bb.y);
            *(float2*)&C[(size_t)row * N + col] = v0;
            *(float2*)&C[(size_t)(row + 8) * N + col] = v1;
        }
    }
}

// ---------------------------------------------------------------------------
// Flash attention: grid (b*h = 64, qtile = 16), 256 threads.
// 128-query tile x 64-kv tile. 8x4 micro tiles for S and O.
// Output rounded to tf32 (consumed only as A of the tf32 out-proj GEMM).
// ---------------------------------------------------------------------------
__global__ __launch_bounds__(256, 2)
void attn_kernel(const float* __restrict__ qkv, float* __restrict__ out) {
    extern __shared__ float sh[];
    float* q_s = sh;                   // [128][68]
    float* kt_s = q_s + 128 * 68;      // [64][68]  transposed: kt_s[d][k]
    float* v_s  = kt_s + 64 * 68;      // [64][68]
    float* p_s  = v_s + 64 * 68;       // [128][68]

    int b  = blockIdx.x >> 4;
    int h  = blockIdx.x & 15;
    int q0 = blockIdx.y << 7;
    int t  = threadIdx.x;
    int tm = (t >> 4) << 3;            // q-rows tm..tm+7 (0..120)
    int tn = (t & 15) << 2;            // kv/d-cols tn..tn+3 (0..60)
    const float scale = 0.125f;        // 1/sqrt(64)

    #pragma unroll
    for (int it = 0; it < 8; it++) {
        int idx = t + (it << 8);
        int r = idx >> 4, c = (idx & 15) << 2;
        size_t g = ((size_t)(b * SEQ + q0 + r)) * 3072 + h * HEAD_DIM + c;
        *(float4*)&q_s[r * 68 + c] = *(const float4*)(qkv + g);
    }

    float o[8][4] = {};
    float m_i[8], l_i[8];
    #pragma unroll
    for (int i = 0; i < 8; i++) { m_i[i] = -1e30f; l_i[i] = 0.f; }

    for (int kt = 0; kt < SEQ / 64; kt++) {
        __syncthreads();
        #pragma unroll
        for (int it = 0; it < 4; it++) {
            int idx = t + (it << 8);
            int r = idx >> 4, c = (idx & 15) << 2;
            size_t g = ((size_t)(b * SEQ + (kt << 6) + r)) * 3072 + INNER + h * HEAD_DIM + c;
            float4 kv4 = *(const float4*)(qkv + g);
            kt_s[(c + 0) * 68 + r] = kv4.x;
            kt_s[(c + 1) * 68 + r] = kv4.y;
            kt_s[(c + 2) * 68 + r] = kv4.z;
            kt_s[(c + 3) * 68 + r] = kv4.w;
            *(float4*)&v_s[r * 68 + c] = *(const float4*)(qkv + g + INNER);
        }
        __syncthreads();

        float s[8][4] = {};
        #pragma unroll
        for (int d = 0; d < HEAD_DIM; d += 4) {
            float4 kb0 = *(const float4*)&kt_s[(d + 0) * 68 + tn];
            float4 kb1 = *(const float4*)&kt_s[(d + 1) * 68 + tn];
            float4 kb2 = *(const float4*)&kt_s[(d + 2) * 68 + tn];
            float4 kb3 = *(const float4*)&kt_s[(d + 3) * 68 + tn];
            #pragma unroll
            for (int i = 0; i < 8; i++) {
                float4 qa = *(const float4*)&q_s[(tm + i) * 68 + d];
                s[i][0] += qa.x * kb0.x + qa.y * kb1.x + qa.z * kb2.x + qa.w * kb3.x;
                s[i][1] += qa.x * kb0.y + qa.y * kb1.y + qa.z * kb2.y + qa.w * kb3.y;
                s[i][2] += qa.x * kb0.z + qa.y * kb1.z + qa.z * kb2.z + qa.w * kb3.z;
                s[i][3] += qa.x * kb0.w + qa.y * kb1.w + qa.z * kb2.w + qa.w * kb3.w;
            }
        }

        #pragma unroll
        for (int i = 0; i < 8; i++) {
            float mt = -1e30f;
            #pragma unroll
            for (int j = 0; j < 4; j++) { s[i][j] *= scale; mt = fmaxf(mt, s[i][j]); }
            #pragma unroll
            for (int o2 = 8; o2; o2 >>= 1) mt = fmaxf(mt, __shfl_xor_sync(0xffffffffu, mt, o2));
            float m_new = fmaxf(m_i[i], mt);
            float corr = __expf(m_i[i] - m_new);
            float ls = 0.f;
            #pragma unroll
            for (int j = 0; j < 4; j++) { s[i][j] = __expf(s[i][j] - m_new); ls += s[i][j]; }
            #pragma unroll
            for (int o2 = 8; o2; o2 >>= 1) ls += __shfl_xor_sync(0xffffffffu, ls, o2);
            l_i[i] = l_i[i] * corr + ls;
            m_i[i] = m_new;
            #pragma unroll
            for (int j = 0; j < 4; j++) o[i][j] *= corr;
            *(float4*)&p_s[(tm + i) * 68 + tn] =
                make_float4(s[i][0], s[i][1], s[i][2], s[i][3]);
        }
        __syncthreads();

        #pragma unroll 4
        for (int k = 0; k < 64; k++) {
            float4 vv = *(const float4*)&v_s[k * 68 + tn];
            float p0 = p_s[(tm + 0) * 68 + k];
            float p1 = p_s[(tm + 1) * 68 + k];
            float p2 = p_s[(tm + 2) * 68 + k];
            float p3 = p_s[(tm + 3) * 68 + k];
            float p4 = p_s[(tm + 4) * 68 + k];
            float p5 = p_s[(tm + 5) * 68 + k];
            float p6 = p_s[(tm + 6) * 68 + k];
            float p7 = p_s[(tm + 7) * 68 + k];
            o[0][0] += p0 * vv.x; o[0][1] += p0 * vv.y; o[0][2] += p0 * vv.z; o[0][3] += p0 * vv.w;
            o[1][0] += p1 * vv.x; o[1][1] += p1 * vv.y; o[1][2] += p1 * vv.z; o[1][3] += p1 * vv.w;
            o[2][0] += p2 * vv.x; o[2][1] += p2 * vv.y; o[2][2] += p2 * vv.z; o[2][3] += p2 * vv.w;
            o[3][0] += p3 * vv.x; o[3][1] += p3 * vv.y; o[3][2] += p3 * vv.z; o[3][3] += p3 * vv.w;
            o[4][0] += p4 * vv.x; o[4][1] += p4 * vv.y; o[4][2] += p4 * vv.z; o[4][3] += p4 * vv.w;
            o[5][0] += p5 * vv.x; o[5][1] += p5 * vv.y; o[5][2] += p5 * vv.z; o[5][3] += p5 * vv.w;
            o[6][0] += p6 * vv.x; o[6][1] += p6 * vv.y; o[6][2] += p6 * vv.z; o[6][3] += p6 * vv.w;
            o[7][0] += p7 * vv.x; o[7][1] += p7 * vv.y; o[7][2] += p7 * vv.z; o[7][3] += p7 * vv.w;
        }
    }

    #pragma unroll
    for (int i = 0; i < 8; i++) {
        float inv = 1.0f / l_i[i];
        size_t obase = ((size_t)(b * SEQ + q0 + tm + i)) * INNER + h * HEAD_DIM + tn;
        float4 ov = make_float4(tf32r(o[i][0] * inv), tf32r(o[i][1] * inv),
                                tf32r(o[i][2] * inv), tf32r(o[i][3] * inv));
        *(float4*)(out + obase) = ov;
    }
}

// ---------------------------------------------------------------------------
extern "C" void kernel_launch(void* const* d_in, const int* in_sizes, int n_in,
                              void* d_out, int out_size) {
    const float* x     = (const float*)d_in[0];
    const float* ln_g  = (const float*)d_in[1];
    const float* ln_b  = (const float*)d_in[2];
    const float* w_qkv = (const float*)d_in[3];
    const float* b_qkv = (const float*)d_in[4];
    const float* w_out = (const float*)d_in[5];
    const float* b_out = (const float*)d_in[6];
    float* out = (float*)d_out;

    float *xn, *qkv, *attn, *wq_t, *wo_t;
    cudaGetSymbolAddress((void**)&xn,   g_xn);
    cudaGetSymbolAddress((void**)&qkv,  g_qkv);
    cudaGetSymbolAddress((void**)&attn, g_attn);
    cudaGetSymbolAddress((void**)&wq_t, g_wqkv_t);
    cudaGetSymbolAddress((void**)&wo_t, g_wout_t);

    cudaFuncSetAttribute(attn_kernel, cudaFuncAttributeMaxDynamicSharedMemorySize, ATTN_SMEM);
    cudaFuncSetAttribute(gemm_tf32_kernel, cudaFuncAttributeMaxDynamicSharedMemorySize, GEMM_SMEM);

    // 0) round weights to tf32 (RNA)
    tf32_cvt_kernel<<<(DIM * 3 * INNER / 4 + 255) / 256, 256>>>(w_qkv, wq_t, DIM * 3 * INNER / 4);
    tf32_cvt_kernel<<<(INNER * DIM / 4 + 255) / 256, 256>>>(w_out, wo_t, INNER * DIM / 4);
    // 1) LayerNorm (tf32-rounded output)
    ln_kernel<<<ROWS, 256>>>(x, ln_g, ln_b, xn);
    // 2) QKV projection: [8192,1024] @ [1024,3072] + bias (tf32 tensor cores)
    gemm_tf32_kernel<<<dim3((3 * INNER) / 128, ROWS / 128), 256, GEMM_SMEM>>>(
        xn, wq_t, b_qkv, qkv, ROWS, 3 * INNER, DIM);
    // 3) Attention (writes [b,s,inner] directly, tf32-rounded)
    attn_kernel<<<dim3(BATCH * HEADS, SEQ / 128), 256, ATTN_SMEM>>>(qkv, attn);
    // 4) Output projection: [8192,1024] @ [1024,1024] + bias (tf32 tensor cores)
    gemm_tf32_kernel<<<dim3(DIM / 128, ROWS / 128), 256, GEMM_SMEM>>>(
        attn, wo_t, b_out, out, ROWS, DIM, INNER);
}

// round 6
// speedup vs baseline: 4.8679x; 2.1260x over previous
#include <cuda_runtime.h>
#include <math.h>
#include <stdint.h>

#define DIM 1024
#define INNER 1024
#define SEQ 2048
#define BATCH 4
#define HEADS 16
#define HEAD_DIM 64
#define ROWS (BATCH*SEQ)            // 8192

// GEMM smem: As[2][128][36] + Bs[2][32][136] floats
#define GEMM_SMEM ((2*128*36 + 2*32*136) * 4)
// attention smem: k[2][64][68] + v[2][64][72] + p[128][68]
#define ATTN_SMEM ((2*64*68 + 2*64*72 + 128*68) * 4)

// Scratch (no runtime allocation allowed)
__device__ float g_xn[(size_t)ROWS * DIM];
__device__ float g_qkv[(size_t)ROWS * 3 * INNER];
__device__ float g_attn[(size_t)ROWS * INNER];
__device__ float g_wqkv_t[(size_t)DIM * 3 * INNER];
__device__ float g_wout_t[(size_t)INNER * DIM];

__device__ __forceinline__ float tf32r(float x) {
    uint32_t u;
    asm("cvt.rna.tf32.f32 %0, %1;" : "=r"(u) : "f"(x));
    return __uint_as_float(u);
}

#define MMA_TF32(d0,d1,d2,d3,a0,a1,a2,a3,b0,b1)                              \
    asm volatile(                                                            \
        "mma.sync.aligned.m16n8k8.row.col.f32.tf32.tf32.f32 "                \
        "{%0,%1,%2,%3}, {%4,%5,%6,%7}, {%8,%9}, {%0,%1,%2,%3};"              \
        : "+f"(d0), "+f"(d1), "+f"(d2), "+f"(d3)                             \
        : "r"(a0), "r"(a1), "r"(a2), "r"(a3), "r"(b0), "r"(b1))

// ---------------------------------------------------------------------------
// Elementwise tf32 rounding (for weights), float4 per thread
// ---------------------------------------------------------------------------
__global__ void tf32_cvt_kernel(const float* __restrict__ in, float* __restrict__ out, int n4) {
    int i = blockIdx.x * 256 + threadIdx.x;
    if (i < n4) {
        float4 v = ((const float4*)in)[i];
        v.x = tf32r(v.x); v.y = tf32r(v.y); v.z = tf32r(v.z); v.w = tf32r(v.w);
        ((float4*)out)[i] = v;
    }
}

// ---------------------------------------------------------------------------
// LayerNorm: one block per row of 1024, 256 threads, tf32-rounded output
// ---------------------------------------------------------------------------
__global__ void ln_kernel(const float* __restrict__ x, const float* __restrict__ g,
                          const float* __restrict__ beta, float* __restrict__ out) {
    int row = blockIdx.x;
    int t = threadIdx.x;
    const float4* xr = (const float4*)(x + (size_t)row * DIM);
    float4 v = xr[t];
    float s  = v.x + v.y + v.z + v.w;
    float ss = v.x*v.x + v.y*v.y + v.z*v.z + v.w*v.w;
    #pragma unroll
    for (int o = 16; o; o >>= 1) {
        s  += __shfl_xor_sync(0xffffffffu, s,  o);
        ss += __shfl_xor_sync(0xffffffffu, ss, o);
    }
    __shared__ float sbuf[8], ssbuf[8];
    __shared__ float mu_s, rstd_s;
    if ((t & 31) == 0) { sbuf[t >> 5] = s; ssbuf[t >> 5] = ss; }
    __syncthreads();
    if (t == 0) {
        float st = 0.f, sst = 0.f;
        #pragma unroll
        for (int i = 0; i < 8; i++) { st += sbuf[i]; sst += ssbuf[i]; }
        float mu  = st * (1.0f / DIM);
        float var = sst * (1.0f / DIM) - mu * mu;
        mu_s = mu;
        rstd_s = rsqrtf(var + 1e-5f);
    }
    __syncthreads();
    float mu = mu_s, rstd = rstd_s;
    float4 gv = ((const float4*)g)[t];
    float4 bv = ((const float4*)beta)[t];
    float4 o4;
    o4.x = tf32r((v.x - mu) * rstd * gv.x + bv.x);
    o4.y = tf32r((v.y - mu) * rstd * gv.y + bv.y);
    o4.z = tf32r((v.z - mu) * rstd * gv.z + bv.z);
    o4.w = tf32r((v.w - mu) * rstd * gv.w + bv.w);
    ((float4*)(out + (size_t)row * DIM))[t] = o4;
}

// ---------------------------------------------------------------------------
// tf32 tensor-core GEMM + bias (unchanged from R4)
// ---------------------------------------------------------------------------
#define CP_ASYNC16(dst, src) \
    asm volatile("cp.async.ca.shared.global [%0], [%1], 16;" :: "r"(dst), "l"(src))

__global__ __launch_bounds__(256, 2)
void gemm_tf32_kernel(const float* __restrict__ A, const float* __restrict__ B,
                      const float* __restrict__ bias, float* __restrict__ C,
                      int M, int N, int K) {
    extern __shared__ float sm[];
    float* As = sm;                       // [2][128][36]
    float* Bs = sm + 2 * 128 * 36;        // [2][32][136]

    int t = threadIdx.x;
    int warp = t >> 5, lane = t & 31;
    int warp_m = warp >> 2;
    int warp_n = warp & 3;
    int qr = lane >> 2;
    int qc = lane & 3;
    int m0 = blockIdx.y << 7;
    int n0 = blockIdx.x << 7;
    int mb = warp_m << 6;
    int nb = warp_n << 5;

    float acc[4][4][4] = {};

    {
        #pragma unroll
        for (int j = 0; j < 4; j++) {
            int idx = t + (j << 8);
            int m = idx >> 3, kc = (idx & 7) << 2;
            uint32_t dst = (uint32_t)__cvta_generic_to_shared(&As[m * 36 + kc]);
            CP_ASYNC16(dst, A + (size_t)(m0 + m) * K + kc);
        }
        #pragma unroll
        for (int j = 0; j < 4; j++) {
            int idx = t + (j << 8);
            int r = idx >> 5, c = (idx & 31) << 2;
            uint32_t dst = (uint32_t)__cvta_generic_to_shared(&Bs[r * 136 + c]);
            CP_ASYNC16(dst, B + (size_t)r * N + n0 + c);
        }
        asm volatile("cp.async.commit_group;");
    }

    int nk = K >> 5;
    for (int k0 = 0; k0 < nk; k0++) {
        asm volatile("cp.async.wait_group 0;");
        __syncthreads();
        int cur = k0 & 1;
        if (k0 + 1 < nk) {
            int nxt = cur ^ 1;
            int kbase = (k0 + 1) << 5;
            float* Asn = As + nxt * 128 * 36;
            float* Bsn = Bs + nxt * 32 * 136;
            #pragma unroll
            for (int j = 0; j < 4; j++) {
                int idx = t + (j << 8);
                int m = idx >> 3, kc = (idx & 7) << 2;
                uint32_t dst = (uint32_t)__cvta_generic_to_shared(&Asn[m * 36 + kc]);
                CP_ASYNC16(dst, A + (size_t)(m0 + m) * K + kbase + kc);
            }
            #pragma unroll
            for (int j = 0; j < 4; j++) {
                int idx = t + (j << 8);
                int r = idx >> 5, c = (idx & 31) << 2;
                uint32_t dst = (uint32_t)__cvta_generic_to_shared(&Bsn[r * 136 + c]);
                CP_ASYNC16(dst, B + (size_t)(kbase + r) * N + n0 + c);
            }
            asm volatile("cp.async.commit_group;");
        }

        const float* Ac = As + cur * 128 * 36;
        const float* Bc = Bs + cur * 32 * 136;

        #pragma unroll
        for (int ks = 0; ks < 4; ks++) {
            int k8 = ks << 3;
            uint32_t af[4][4], bf[4][2];
            #pragma unroll
            for (int mt = 0; mt < 4; mt++) {
                const float* ap = Ac + (mb + (mt << 4) + qr) * 36 + k8 + qc;
                af[mt][0] = __float_as_uint(ap[0]);
                af[mt][1] = __float_as_uint(ap[8 * 36]);
                af[mt][2] = __float_as_uint(ap[4]);
                af[mt][3] = __float_as_uint(ap[8 * 36 + 4]);
            }
            #pragma unroll
            for (int nt = 0; nt < 4; nt++) {
                const float* bp = Bc + (k8 + qc) * 136 + nb + (nt << 3) + qr;
                bf[nt][0] = __float_as_uint(bp[0]);
                bf[nt][1] = __float_as_uint(bp[4 * 136]);
            }
            #pragma unroll
            for (int mt = 0; mt < 4; mt++)
                #pragma unroll
                for (int nt = 0; nt < 4; nt++)
                    MMA_TF32(acc[mt][nt][0], acc[mt][nt][1], acc[mt][nt][2], acc[mt][nt][3],
                             af[mt][0], af[mt][1], af[mt][2], af[mt][3],
                             bf[nt][0], bf[nt][1]);
        }
        __syncthreads();
    }

    #pragma unroll
    for (int nt = 0; nt < 4; nt++) {
        int col = n0 + nb + (nt << 3) + (qc << 1);
        float2 bb = *(const float2*)&bias[col];
        #pragma unroll
        for (int mt = 0; mt < 4; mt++) {
            int row = m0 + mb + (mt << 4) + qr;
            float2 v0 = make_float2(acc[mt][nt][0] + bb.x, acc[mt][nt][1] + bb.y);
            float2 v1 = make_float2(acc[mt][nt][2] + bb.x, acc[mt][nt][3] + bb.y);
            *(float2*)&C[(size_t)row * N + col] = v0;
            *(float2*)&C[(size_t)(row + 8) * N + col] = v1;
        }
    }
}

// ---------------------------------------------------------------------------
// Tensor-core flash attention: grid (b*h=64, qtile=16), 256 threads (8 warps).
// 128q x 64kv tile. Each warp: 16 q-rows x full 64 kv -> warp-local softmax.
// tf32 mma for S=QK^T and O=PV. K/V double-buffered via register prefetch.
// Smem strides: K/P/Q-staging 68 (banks qr*4+qc), V 72 (banks qc*8+qr).
// ---------------------------------------------------------------------------
#define KSTR 68
#define VSTR 72
#define PSTR 68

__global__ __launch_bounds__(256)
void attn_kernel(const float* __restrict__ qkv, float* __restrict__ out) {
    extern __shared__ float sh[];
    float* k_s = sh;                     // [2][64][KSTR]
    float* v_s = k_s + 2 * 64 * KSTR;    // [2][64][VSTR]
    float* p_s = v_s + 2 * 64 * VSTR;    // [128][PSTR]

    int b  = blockIdx.x >> 4;
    int h  = blockIdx.x & 15;
    int q0 = blockIdx.y << 7;
    int t  = threadIdx.x;
    int warp = t >> 5, lane = t & 31;
    int qr = lane >> 2, qc = lane & 3;
    int w16 = warp << 4;
    const float scale = 0.125f;

    // ---- Stage Q (tf32-rounded) through p_s, then lift fragments to regs
    #pragma unroll
    for (int it = 0; it < 8; it++) {
        int idx = t + (it << 8);
        int r = idx >> 4, c = (idx & 15) << 2;
        size_t g = ((size_t)(b * SEQ + q0 + r)) * 3072 + h * HEAD_DIM + c;
        float4 v = *(const float4*)(qkv + g);
        p_s[r * PSTR + c + 0] = tf32r(v.x);
        p_s[r * PSTR + c + 1] = tf32r(v.y);
        p_s[r * PSTR + c + 2] = tf32r(v.z);
        p_s[r * PSTR + c + 3] = tf32r(v.w);
    }
    __syncthreads();

    uint32_t qf[8][4];
    #pragma unroll
    for (int ks = 0; ks < 8; ks++) {
        int k8 = ks << 3;
        qf[ks][0] = __float_as_uint(p_s[(w16 + qr) * PSTR + k8 + qc]);
        qf[ks][1] = __float_as_uint(p_s[(w16 + qr + 8) * PSTR + k8 + qc]);
        qf[ks][2] = __float_as_uint(p_s[(w16 + qr) * PSTR + k8 + qc + 4]);
        qf[ks][3] = __float_as_uint(p_s[(w16 + qr + 8) * PSTR + k8 + qc + 4]);
    }
    __syncthreads();

    // loader mapping: 4 float4 each for K and V per thread
    int lr = t >> 4;                 // 0..15 (row base, +16 per it)
    int lc = (t & 15) << 2;          // 0..60

    // ---- prologue: KV tile 0
    float4 kreg[4], vreg[4];
    {
        #pragma unroll
        for (int it = 0; it < 4; it++) {
            int r = lr + (it << 4);
            size_t g = ((size_t)(b * SEQ + r)) * 3072 + INNER + h * HEAD_DIM + lc;
            kreg[it] = *(const float4*)(qkv + g);
            vreg[it] = *(const float4*)(qkv + g + INNER);
        }
        #pragma unroll
        for (int it = 0; it < 4; it++) {
            int r = lr + (it << 4);
            float* kd = &k_s[r * KSTR + lc];
            float* vd = &v_s[r * VSTR + lc];
            kd[0] = tf32r(kreg[it].x); kd[1] = tf32r(kreg[it].y);
            kd[2] = tf32r(kreg[it].z); kd[3] = tf32r(kreg[it].w);
            vd[0] = tf32r(vreg[it].x); vd[1] = tf32r(vreg[it].y);
            vd[2] = tf32r(vreg[it].z); vd[3] = tf32r(vreg[it].w);
        }
    }
    __syncthreads();

    float o[8][4] = {};
    float m0r = -1e30f, m1r = -1e30f, l0r = 0.f, l1r = 0.f;

    for (int kt = 0; kt < SEQ / 64; kt++) {
        int cur = kt & 1;
        const float* kc_ = k_s + cur * 64 * KSTR;
        const float* vc_ = v_s + cur * 64 * VSTR;

        // prefetch next KV tile into regs (used at loop bottom)
        if (kt + 1 < SEQ / 64) {
            #pragma unroll
            for (int it = 0; it < 4; it++) {
                int r = lr + (it << 4);
                size_t g = ((size_t)(b * SEQ + ((kt + 1) << 6) + r)) * 3072
                         + INNER + h * HEAD_DIM + lc;
                kreg[it] = *(const float4*)(qkv + g);
                vreg[it] = *(const float4*)(qkv + g + INNER);
            }
        }

        // ---- S = Q K^T : per warp 16x64
        float s[8][4] = {};
        #pragma unroll
        for (int ks = 0; ks < 8; ks++) {
            int k8 = ks << 3;
            #pragma unroll
            for (int nt = 0; nt < 8; nt++) {
                uint32_t b0 = __float_as_uint(kc_[((nt << 3) + qr) * KSTR + k8 + qc]);
                uint32_t b1 = __float_as_uint(kc_[((nt << 3) + qr) * KSTR + k8 + qc + 4]);
                MMA_TF32(s[nt][0], s[nt][1], s[nt][2], s[nt][3],
                         qf[ks][0], qf[ks][1], qf[ks][2], qf[ks][3], b0, b1);
            }
        }

        // ---- online softmax (rows qr and qr+8; reduce over 4 qc lanes)
        float mt0 = -1e30f, mt1 = -1e30f;
        #pragma unroll
        for (int nt = 0; nt < 8; nt++) {
            s[nt][0] *= scale; s[nt][1] *= scale; s[nt][2] *= scale; s[nt][3] *= scale;
            mt0 = fmaxf(mt0, fmaxf(s[nt][0], s[nt][1]));
            mt1 = fmaxf(mt1, fmaxf(s[nt][2], s[nt][3]));
        }
        mt0 = fmaxf(mt0, __shfl_xor_sync(0xffffffffu, mt0, 1));
        mt0 = fmaxf(mt0, __shfl_xor_sync(0xffffffffu, mt0, 2));
        mt1 = fmaxf(mt1, __shfl_xor_sync(0xffffffffu, mt1, 1));
        mt1 = fmaxf(mt1, __shfl_xor_sync(0xffffffffu, mt1, 2));
        float mn0 = fmaxf(m0r, mt0), mn1 = fmaxf(m1r, mt1);
        float corr0 = __expf(m0r - mn0), corr1 = __expf(m1r - mn1);
        float ls0 = 0.f, ls1 = 0.f;
        #pragma unroll
        for (int nt = 0; nt < 8; nt++) {
            s[nt][0] = __expf(s[nt][0] - mn0); ls0 += s[nt][0];
            s[nt][1] = __expf(s[nt][1] - mn0); ls0 += s[nt][1];
            s[nt][2] = __expf(s[nt][2] - mn1); ls1 += s[nt][2];
            s[nt][3] = __expf(s[nt][3] - mn1); ls1 += s[nt][3];
        }
        ls0 += __shfl_xor_sync(0xffffffffu, ls0, 1);
        ls0 += __shfl_xor_sync(0xffffffffu, ls0, 2);
        ls1 += __shfl_xor_sync(0xffffffffu, ls1, 1);
        ls1 += __shfl_xor_sync(0xffffffffu, ls1, 2);
        l0r = l0r * corr0 + ls0;  m0r = mn0;
        l1r = l1r * corr1 + ls1;  m1r = mn1;
        #pragma unroll
        for (int nt = 0; nt < 8; nt++) {
            o[nt][0] *= corr0; o[nt][1] *= corr0;
            o[nt][2] *= corr1; o[nt][3] *= corr1;
        }

        // ---- write P (tf32) to warp-private p_s rows
        #pragma unroll
        for (int nt = 0; nt < 8; nt++) {
            int colp = (nt << 3) + (qc << 1);
            *(float2*)&p_s[(w16 + qr) * PSTR + colp] =
                make_float2(tf32r(s[nt][0]), tf32r(s[nt][1]));
            *(float2*)&p_s[(w16 + qr + 8) * PSTR + colp] =
                make_float2(tf32r(s[nt][2]), tf32r(s[nt][3]));
        }
        __syncwarp();

        // ---- O += P V : per warp 16x64
        #pragma unroll
        for (int ks = 0; ks < 8; ks++) {
            int k8 = ks << 3;
            uint32_t a0 = __float_as_uint(p_s[(w16 + qr) * PSTR + k8 + qc]);
            uint32_t a1 = __float_as_uint(p_s[(w16 + qr + 8) * PSTR + k8 + qc]);
            uint32_t a2 = __float_as_uint(p_s[(w16 + qr) * PSTR + k8 + qc + 4]);
            uint32_t a3 = __float_as_uint(p_s[(w16 + qr + 8) * PSTR + k8 + qc + 4]);
            #pragma unroll
            for (int nt = 0; nt < 8; nt++) {
                uint32_t b0 = __float_as_uint(vc_[(k8 + qc) * VSTR + (nt << 3) + qr]);
                uint32_t b1 = __float_as_uint(vc_[(k8 + qc + 4) * VSTR + (nt << 3) + qr]);
                MMA_TF32(o[nt][0], o[nt][1], o[nt][2], o[nt][3], a0, a1, a2, a3, b0, b1);
            }
        }
        __syncwarp();

        // ---- store prefetched tile into the other buffer
        if (kt + 1 < SEQ / 64) {
            int nxt = cur ^ 1;
            float* kn = k_s + nxt * 64 * KSTR;
            float* vn = v_s + nxt * 64 * VSTR;
            #pragma unroll
            for (int it = 0; it < 4; it++) {
                int r = lr + (it << 4);
                float* kd = &kn[r * KSTR + lc];
                float* vd = &vn[r * VSTR + lc];
                kd[0] = tf32r(kreg[it].x); kd[1] = tf32r(kreg[it].y);
                kd[2] = tf32r(kreg[it].z); kd[3] = tf32r(kreg[it].w);
                vd[0] = tf32r(vreg[it].x); vd[1] = tf32r(vreg[it].y);
                vd[2] = tf32r(vreg[it].z); vd[3] = tf32r(vreg[it].w);
            }
        }
        __syncthreads();
    }

    // ---- finalize: /l, tf32-round, write [b, s, h*64+d]
    float inv0 = 1.0f / l0r, inv1 = 1.0f / l1r;
    #pragma unroll
    for (int nt = 0; nt < 8; nt++) {
        int col = h * HEAD_DIM + (nt << 3) + (qc << 1);
        size_t r0 = ((size_t)(b * SEQ + q0 + w16 + qr)) * INNER + col;
        size_t r1 = ((size_t)(b * SEQ + q0 + w16 + qr + 8)) * INNER + col;
        *(float2*)&out[r0] = make_float2(tf32r(o[nt][0] * inv0), tf32r(o[nt][1] * inv0));
        *(float2*)&out[r1] = make_float2(tf32r(o[nt][2] * inv1), tf32r(o[nt][3] * inv1));
    }
}

// ---------------------------------------------------------------------------
extern "C" void kernel_launch(void* const* d_in, const int* in_sizes, int n_in,
                              void* d_out, int out_size) {
    const float* x     = (const float*)d_in[0];
    const float* ln_g  = (const float*)d_in[1];
    const float* ln_b  = (const float*)d_in[2];
    const float* w_qkv = (const float*)d_in[3];
    const float* b_qkv = (const float*)d_in[4];
    const float* w_out = (const float*)d_in[5];
    const float* b_out = (const float*)d_in[6];
    float* out = (float*)d_out;

    float *xn, *qkv, *attn, *wq_t, *wo_t;
    cudaGetSymbolAddress((void**)&xn,   g_xn);
    cudaGetSymbolAddress((void**)&qkv,  g_qkv);
    cudaGetSymbolAddress((void**)&attn, g_attn);
    cudaGetSymbolAddress((void**)&wq_t, g_wqkv_t);
    cudaGetSymbolAddress((void**)&wo_t, g_wout_t);

    cudaFuncSetAttribute(attn_kernel, cudaFuncAttributeMaxDynamicSharedMemorySize, ATTN_SMEM);
    cudaFuncSetAttribute(gemm_tf32_kernel, cudaFuncAttributeMaxDynamicSharedMemorySize, GEMM_SMEM);

    // 0) round weights to tf32 (RNA)
    tf32_cvt_kernel<<<(DIM * 3 * INNER / 4 + 255) / 256, 256>>>(w_qkv, wq_t, DIM * 3 * INNER / 4);
    tf32_cvt_kernel<<<(INNER * DIM / 4 + 255) / 256, 256>>>(w_out, wo_t, INNER * DIM / 4);
    // 1) LayerNorm (tf32-rounded output)
    ln_kernel<<<ROWS, 256>>>(x, ln_g, ln_b, xn);
    // 2) QKV projection (tf32 tensor cores)
    gemm_tf32_kernel<<<dim3((3 * INNER) / 128, ROWS / 128), 256, GEMM_SMEM>>>(
        xn, wq_t, b_qkv, qkv, ROWS, 3 * INNER, DIM);
    // 3) Attention (tensor-core flash, writes [b,s,inner] directly)
    attn_kernel<<<dim3(BATCH * HEADS, SEQ / 128), 256, ATTN_SMEM>>>(qkv, attn);
    // 4) Output projection (tf32 tensor cores)
    gemm_tf32_kernel<<<dim3(DIM / 128, ROWS / 128), 256, GEMM_SMEM>>>(
        attn, wo_t, b_out, out, ROWS, DIM, INNER);
}

// round 7
// speedup vs baseline: 5.1956x; 1.0673x over previous
#include <cuda_runtime.h>
#include <math.h>
#include <stdint.h>

#define DIM 1024
#define INNER 1024
#define SEQ 2048
#define BATCH 4
#define HEADS 16
#define HEAD_DIM 64
#define ROWS (BATCH*SEQ)            // 8192

// GEMM smem: As[2][128][36] + Bs[2][128][36] floats
#define GEMM_SMEM ((2*128*36 + 2*128*36) * 4)
// attention smem: k[2][64][68] + v[2][64][72] + p[128][68]
#define ATTN_SMEM ((2*64*68 + 2*64*72 + 128*68) * 4)

// Scratch (no runtime allocation allowed)
__device__ float g_xn[(size_t)ROWS * DIM];
__device__ float g_qkv[(size_t)ROWS * 3 * INNER];
__device__ float g_attn[(size_t)ROWS * INNER];
__device__ float g_wqkv_t[(size_t)DIM * 3 * INNER];   // [N=3072][K=1024]
__device__ float g_wout_t[(size_t)INNER * DIM];       // [N=1024][K=1024]

__device__ __forceinline__ float tf32r(float x) {
    uint32_t u;
    asm("cvt.rna.tf32.f32 %0, %1;" : "=r"(u) : "f"(x));
    return __uint_as_float(u);
}

#define MMA_TF32(d0,d1,d2,d3,a0,a1,a2,a3,b0,b1)                              \
    asm volatile(                                                            \
        "mma.sync.aligned.m16n8k8.row.col.f32.tf32.tf32.f32 "                \
        "{%0,%1,%2,%3}, {%4,%5,%6,%7}, {%8,%9}, {%0,%1,%2,%3};"              \
        : "+f"(d0), "+f"(d1), "+f"(d2), "+f"(d3)                             \
        : "r"(a0), "r"(a1), "r"(a2), "r"(a3), "r"(b0), "r"(b1))

__device__ __forceinline__ void ldsm4(uint32_t& r0, uint32_t& r1,
                                      uint32_t& r2, uint32_t& r3, uint32_t a) {
    asm volatile("ldmatrix.sync.aligned.m8n8.x4.shared.b16 {%0,%1,%2,%3}, [%4];"
                 : "=r"(r0), "=r"(r1), "=r"(r2), "=r"(r3) : "r"(a));
}

#define CP_ASYNC16(dst, src) \
    asm volatile("cp.async.ca.shared.global [%0], [%1], 16;" :: "r"(dst), "l"(src))

// ---------------------------------------------------------------------------
// Weight transpose + tf32 round: in[K][N] -> out[N][K]
// ---------------------------------------------------------------------------
__global__ void transpose_tf32_kernel(const float* __restrict__ in, float* __restrict__ out,
                                      int K, int N) {
    __shared__ float tile[32][33];
    int n0 = blockIdx.x << 5, k0 = blockIdx.y << 5;
    int tx = threadIdx.x, ty = threadIdx.y;
    #pragma unroll
    for (int j = 0; j < 4; j++)
        tile[ty + 8 * j][tx] = in[(size_t)(k0 + ty + 8 * j) * N + n0 + tx];
    __syncthreads();
    #pragma unroll
    for (int j = 0; j < 4; j++)
        out[(size_t)(n0 + ty + 8 * j) * K + k0 + tx] = tf32r(tile[tx][ty + 8 * j]);
}

// ---------------------------------------------------------------------------
// LayerNorm: one block per row of 1024, 256 threads, tf32-rounded output
// ---------------------------------------------------------------------------
__global__ void ln_kernel(const float* __restrict__ x, const float* __restrict__ g,
                          const float* __restrict__ beta, float* __restrict__ out) {
    int row = blockIdx.x;
    int t = threadIdx.x;
    const float4* xr = (const float4*)(x + (size_t)row * DIM);
    float4 v = xr[t];
    float s  = v.x + v.y + v.z + v.w;
    float ss = v.x*v.x + v.y*v.y + v.z*v.z + v.w*v.w;
    #pragma unroll
    for (int o = 16; o; o >>= 1) {
        s  += __shfl_xor_sync(0xffffffffu, s,  o);
        ss += __shfl_xor_sync(0xffffffffu, ss, o);
    }
    __shared__ float sbuf[8], ssbuf[8];
    __shared__ float mu_s, rstd_s;
    if ((t & 31) == 0) { sbuf[t >> 5] = s; ssbuf[t >> 5] = ss; }
    __syncthreads();
    if (t == 0) {
        float st = 0.f, sst = 0.f;
        #pragma unroll
        for (int i = 0; i < 8; i++) { st += sbuf[i]; sst += ssbuf[i]; }
        float mu  = st * (1.0f / DIM);
        float var = sst * (1.0f / DIM) - mu * mu;
        mu_s = mu;
        rstd_s = rsqrtf(var + 1e-5f);
    }
    __syncthreads();
    float mu = mu_s, rstd = rstd_s;
    float4 gv = ((const float4*)g)[t];
    float4 bv = ((const float4*)beta)[t];
    float4 o4;
    o4.x = tf32r((v.x - mu) * rstd * gv.x + bv.x);
    o4.y = tf32r((v.y - mu) * rstd * gv.y + bv.y);
    o4.z = tf32r((v.z - mu) * rstd * gv.z + bv.z);
    o4.w = tf32r((v.w - mu) * rstd * gv.w + bv.w);
    ((float4*)(out + (size_t)row * DIM))[t] = o4;
}

// ---------------------------------------------------------------------------
// tf32 tensor-core GEMM + bias: C[M,N] = A[M,K] @ Bt[N,K]^T + bias[N]
// A and Bt both K-major. 128x128x32 tile, 256 threads, warp grid 2x4,
// warp tile 64x32, mma.m16n8k8, ldmatrix fragment loads, cp.async 2-stage.
// ---------------------------------------------------------------------------
__global__ __launch_bounds__(256, 2)
void gemm_tf32_kernel(const float* __restrict__ A, const float* __restrict__ Bt,
                      const float* __restrict__ bias, float* __restrict__ C,
                      int M, int N, int K) {
    extern __shared__ float sm[];
    float* As = sm;                       // [2][128][36]
    float* Bs = sm + 2 * 128 * 36;        // [2][128][36]

    int t = threadIdx.x;
    int warp = t >> 5, lane = t & 31;
    int warp_m = warp >> 2;               // 0..1
    int warp_n = warp & 3;                // 0..3
    int qr = lane >> 2;                   // 0..7
    int qc = lane & 3;                    // 0..3
    int m0 = blockIdx.y << 7;
    int n0 = blockIdx.x << 7;
    int mb = warp_m << 6;
    int nb = warp_n << 5;

    uint32_t as_base = (uint32_t)__cvta_generic_to_shared(As);
    uint32_t bs_base = (uint32_t)__cvta_generic_to_shared(Bs);

    // ldmatrix per-lane fragment offsets (in floats)
    int lr8 = lane & 7;
    // A pattern: r0/r1 rows +0/+8 (bit3), r2/r3 cols +4 (bit4)
    int aoff = (mb + (((lane >> 3) & 1) << 3) + lr8) * 36 + ((lane >> 4) << 2);
    // B pattern: r0/r1 cols +0/+4 (bit3), r2/r3 rows +8 (bit4)
    int boff = (nb + ((lane >> 4) << 3) + lr8) * 36 + (((lane >> 3) & 1) << 2);

    // global->smem mapping: idx -> (row = idx>>3, kc = (idx&7)*4)
    float acc[4][4][4] = {};

    {
        #pragma unroll
        for (int j = 0; j < 4; j++) {
            int idx = t + (j << 8);
            int r = idx >> 3, kc = (idx & 7) << 2;
            CP_ASYNC16(as_base + (uint32_t)(r * 36 + kc) * 4,
                       A + (size_t)(m0 + r) * K + kc);
            CP_ASYNC16(bs_base + (uint32_t)(r * 36 + kc) * 4,
                       Bt + (size_t)(n0 + r) * K + kc);
        }
        asm volatile("cp.async.commit_group;");
    }

    int nk = K >> 5;
    for (int k0 = 0; k0 < nk; k0++) {
        asm volatile("cp.async.wait_group 0;");
        __syncthreads();
        int cur = k0 & 1;
        if (k0 + 1 < nk) {
            int nxt = cur ^ 1;
            int kbase = (k0 + 1) << 5;
            uint32_t asn = as_base + (uint32_t)(nxt * 128 * 36) * 4;
            uint32_t bsn = bs_base + (uint32_t)(nxt * 128 * 36) * 4;
            #pragma unroll
            for (int j = 0; j < 4; j++) {
                int idx = t + (j << 8);
                int r = idx >> 3, kc = (idx & 7) << 2;
                CP_ASYNC16(asn + (uint32_t)(r * 36 + kc) * 4,
                           A + (size_t)(m0 + r) * K + kbase + kc);
                CP_ASYNC16(bsn + (uint32_t)(r * 36 + kc) * 4,
                           Bt + (size_t)(n0 + r) * K + kbase + kc);
            }
            asm volatile("cp.async.commit_group;");
        }

        uint32_t ac = as_base + (uint32_t)(cur * 128 * 36) * 4;
        uint32_t bc = bs_base + (uint32_t)(cur * 128 * 36) * 4;

        #pragma unroll
        for (int ks = 0; ks < 4; ks++) {
            int k8 = ks << 3;
            uint32_t af[4][4], bf[4][2];
            #pragma unroll
            for (int mt = 0; mt < 4; mt++)
                ldsm4(af[mt][0], af[mt][1], af[mt][2], af[mt][3],
                      ac + (uint32_t)(aoff + mt * 16 * 36 + k8) * 4);
            #pragma unroll
            for (int ntp = 0; ntp < 2; ntp++)
                ldsm4(bf[2*ntp][0], bf[2*ntp][1], bf[2*ntp+1][0], bf[2*ntp+1][1],
                      bc + (uint32_t)(boff + ntp * 16 * 36 + k8) * 4);
            #pragma unroll
            for (int mt = 0; mt < 4; mt++)
                #pragma unroll
                for (int nt = 0; nt < 4; nt++)
                    MMA_TF32(acc[mt][nt][0], acc[mt][nt][1], acc[mt][nt][2], acc[mt][nt][3],
                             af[mt][0], af[mt][1], af[mt][2], af[mt][3],
                             bf[nt][0], bf[nt][1]);
        }
        __syncthreads();
    }

    #pragma unroll
    for (int nt = 0; nt < 4; nt++) {
        int col = n0 + nb + (nt << 3) + (qc << 1);
        float2 bb = *(const float2*)&bias[col];
        #pragma unroll
        for (int mt = 0; mt < 4; mt++) {
            int row = m0 + mb + (mt << 4) + qr;
            float2 v0 = make_float2(acc[mt][nt][0] + bb.x, acc[mt][nt][1] + bb.y);
            float2 v1 = make_float2(acc[mt][nt][2] + bb.x, acc[mt][nt][3] + bb.y);
            *(float2*)&C[(size_t)row * N + col] = v0;
            *(float2*)&C[(size_t)(row + 8) * N + col] = v1;
        }
    }
}

// ---------------------------------------------------------------------------
// Tensor-core flash attention with ldmatrix fragment loads.
// grid (b*h=64, qtile=16), 256 threads (8 warps), 128q x 64kv tile.
// Q pre-scaled by 1/8 at staging. K frags via ldmatrix; V frags scalar.
// ---------------------------------------------------------------------------
#define KSTR 68
#define VSTR 72
#define PSTR 68

__global__ __launch_bounds__(256)
void attn_kernel(const float* __restrict__ qkv, float* __restrict__ out) {
    extern __shared__ float sh[];
    float* k_s = sh;                     // [2][64][KSTR]
    float* v_s = k_s + 2 * 64 * KSTR;    // [2][64][VSTR]
    float* p_s = v_s + 2 * 64 * VSTR;    // [128][PSTR]

    int b  = blockIdx.x >> 4;
    int h  = blockIdx.x & 15;
    int q0 = blockIdx.y << 7;
    int t  = threadIdx.x;
    int warp = t >> 5, lane = t & 31;
    int qr = lane >> 2, qc = lane & 3;
    int w16 = warp << 4;
    int lr8 = lane & 7;

    uint32_t ks_base = (uint32_t)__cvta_generic_to_shared(k_s);
    uint32_t ps_base = (uint32_t)__cvta_generic_to_shared(p_s);

    // ---- Stage Q (scaled by 1/8, tf32-rounded) into p_s, lift frags via ldmatrix
    #pragma unroll
    for (int it = 0; it < 8; it++) {
        int idx = t + (it << 8);
        int r = idx >> 4, c = (idx & 15) << 2;
        size_t g = ((size_t)(b * SEQ + q0 + r)) * 3072 + h * HEAD_DIM + c;
        float4 v = *(const float4*)(qkv + g);
        p_s[r * PSTR + c + 0] = tf32r(v.x * 0.125f);
        p_s[r * PSTR + c + 1] = tf32r(v.y * 0.125f);
        p_s[r * PSTR + c + 2] = tf32r(v.z * 0.125f);
        p_s[r * PSTR + c + 3] = tf32r(v.w * 0.125f);
    }
    __syncthreads();

    // A-operand ldmatrix offset pattern (rows +8 on bit3, cols +4 on bit4)
    int qoff = (w16 + (((lane >> 3) & 1) << 3) + lr8) * PSTR + ((lane >> 4) << 2);
    uint32_t qf[8][4];
    #pragma unroll
    for (int ks = 0; ks < 8; ks++)
        ldsm4(qf[ks][0], qf[ks][1], qf[ks][2], qf[ks][3],
              ps_base + (uint32_t)(qoff + (ks << 3)) * 4);
    __syncthreads();

    // B-operand ldmatrix offset pattern for K (cols +4 on bit3, rows +8 on bit4)
    int koff = (((lane >> 4) << 3) + lr8) * KSTR + (((lane >> 3) & 1) << 2);

    // loader mapping: 4 float4 each for K and V per thread
    int lr = t >> 4;                 // 0..15 (row base, +16 per it)
    int lc = (t & 15) << 2;          // 0..60

    // ---- prologue: KV tile 0
    float4 kreg[4], vreg[4];
    {
        #pragma unroll
        for (int it = 0; it < 4; it++) {
            int r = lr + (it << 4);
            size_t g = ((size_t)(b * SEQ + r)) * 3072 + INNER + h * HEAD_DIM + lc;
            kreg[it] = *(const float4*)(qkv + g);
            vreg[it] = *(const float4*)(qkv + g + INNER);
        }
        #pragma unroll
        for (int it = 0; it < 4; it++) {
            int r = lr + (it << 4);
            float* kd = &k_s[r * KSTR + lc];
            float* vd = &v_s[r * VSTR + lc];
            kd[0] = tf32r(kreg[it].x); kd[1] = tf32r(kreg[it].y);
            kd[2] = tf32r(kreg[it].z); kd[3] = tf32r(kreg[it].w);
            vd[0] = tf32r(vreg[it].x); vd[1] = tf32r(vreg[it].y);
            vd[2] = tf32r(vreg[it].z); vd[3] = tf32r(vreg[it].w);
        }
    }
    __syncthreads();

    float o[8][4] = {};
    float m0r = -1e30f, m1r = -1e30f, l0r = 0.f, l1r = 0.f;

    for (int kt = 0; kt < SEQ / 64; kt++) {
        int cur = kt & 1;
        uint32_t kc_b = ks_base + (uint32_t)(cur * 64 * KSTR) * 4;
        const float* vc_ = v_s + cur * 64 * VSTR;

        if (kt + 1 < SEQ / 64) {
            #pragma unroll
            for (int it = 0; it < 4; it++) {
                int r = lr + (it << 4);
                size_t g = ((size_t)(b * SEQ + ((kt + 1) << 6) + r)) * 3072
                         + INNER + h * HEAD_DIM + lc;
                kreg[it] = *(const float4*)(qkv + g);
                vreg[it] = *(const float4*)(qkv + g + INNER);
            }
        }

        // ---- S = Q K^T : per warp 16x64, K frags via ldmatrix
        float s[8][4] = {};
        #pragma unroll
        for (int ks = 0; ks < 8; ks++) {
            int k8 = ks << 3;
            #pragma unroll
            for (int ntp = 0; ntp < 4; ntp++) {
                uint32_t b00, b01, b10, b11;
                ldsm4(b00, b01, b10, b11,
                      kc_b + (uint32_t)(koff + ntp * 16 * KSTR + k8) * 4);
                MMA_TF32(s[2*ntp][0], s[2*ntp][1], s[2*ntp][2], s[2*ntp][3],
                         qf[ks][0], qf[ks][1], qf[ks][2], qf[ks][3], b00, b01);
                MMA_TF32(s[2*ntp+1][0], s[2*ntp+1][1], s[2*ntp+1][2], s[2*ntp+1][3],
                         qf[ks][0], qf[ks][1], qf[ks][2], qf[ks][3], b10, b11);
            }
        }

        // ---- online softmax (rows qr, qr+8; reduce over 4 qc lanes)
        float mt0 = -1e30f, mt1 = -1e30f;
        #pragma unroll
        for (int nt = 0; nt < 8; nt++) {
            mt0 = fmaxf(mt0, fmaxf(s[nt][0], s[nt][1]));
            mt1 = fmaxf(mt1, fmaxf(s[nt][2], s[nt][3]));
        }
        mt0 = fmaxf(mt0, __shfl_xor_sync(0xffffffffu, mt0, 1));
        mt0 = fmaxf(mt0, __shfl_xor_sync(0xffffffffu, mt0, 2));
        mt1 = fmaxf(mt1, __shfl_xor_sync(0xffffffffu, mt1, 1));
        mt1 = fmaxf(mt1, __shfl_xor_sync(0xffffffffu, mt1, 2));
        float mn0 = fmaxf(m0r, mt0), mn1 = fmaxf(m1r, mt1);
        float corr0 = __expf(m0r - mn0), corr1 = __expf(m1r - mn1);
        float ls0 = 0.f, ls1 = 0.f;
        #pragma unroll
        for (int nt = 0; nt < 8; nt++) {
            s[nt][0] = __expf(s[nt][0] - mn0); ls0 += s[nt][0];
            s[nt][1] = __expf(s[nt][1] - mn0); ls0 += s[nt][1];
            s[nt][2] = __expf(s[nt][2] - mn1); ls1 += s[nt][2];
            s[nt][3] = __expf(s[nt][3] - mn1); ls1 += s[nt][3];
        }
        ls0 += __shfl_xor_sync(0xffffffffu, ls0, 1);
        ls0 += __shfl_xor_sync(0xffffffffu, ls0, 2);
        ls1 += __shfl_xor_sync(0xffffffffu, ls1, 1);
        ls1 += __shfl_xor_sync(0xffffffffu, ls1, 2);
        l0r = l0r * corr0 + ls0;  m0r = mn0;
        l1r = l1r * corr1 + ls1;  m1r = mn1;
        #pragma unroll
        for (int nt = 0; nt < 8; nt++) {
            o[nt][0] *= corr0; o[nt][1] *= corr0;
            o[nt][2] *= corr1; o[nt][3] *= corr1;
        }

        // ---- write P (tf32) to warp-private p_s rows
        #pragma unroll
        for (int nt = 0; nt < 8; nt++) {
            int colp = (nt << 3) + (qc << 1);
            *(float2*)&p_s[(w16 + qr) * PSTR + colp] =
                make_float2(tf32r(s[nt][0]), tf32r(s[nt][1]));
            *(float2*)&p_s[(w16 + qr + 8) * PSTR + colp] =
                make_float2(tf32r(s[nt][2]), tf32r(s[nt][3]));
        }
        __syncwarp();

        // ---- O += P V : per warp 16x64
        #pragma unroll
        for (int ks = 0; ks < 8; ks++) {
            int k8 = ks << 3;
            uint32_t a0 = __float_as_uint(p_s[(w16 + qr) * PSTR + k8 + qc]);
            uint32_t a1 = __float_as_uint(p_s[(w16 + qr + 8) * PSTR + k8 + qc]);
            uint32_t a2 = __float_as_uint(p_s[(w16 + qr) * PSTR + k8 + qc + 4]);
            uint32_t a3 = __float_as_uint(p_s[(w16 + qr + 8) * PSTR + k8 + qc + 4]);
            #pragma unroll
            for (int nt = 0; nt < 8; nt++) {
                uint32_t b0 = __float_as_uint(vc_[(k8 + qc) * VSTR + (nt << 3) + qr]);
                uint32_t b1 = __float_as_uint(vc_[(k8 + qc + 4) * VSTR + (nt << 3) + qr]);
                MMA_TF32(o[nt][0], o[nt][1], o[nt][2], o[nt][3], a0, a1, a2, a3, b0, b1);
            }
        }
        __syncwarp();

        // ---- store prefetched tile into the other buffer
        if (kt + 1 < SEQ / 64) {
            int nxt = cur ^ 1;
            float* kn = k_s + nxt * 64 * KSTR;
            float* vn = v_s + nxt * 64 * VSTR;
            #pragma unroll
            for (int it = 0; it < 4; it++) {
                int r = lr + (it << 4);
                float* kd = &kn[r * KSTR + lc];
                float* vd = &vn[r * VSTR + lc];
                kd[0] = tf32r(kreg[it].x); kd[1] = tf32r(kreg[it].y);
                kd[2] = tf32r(kreg[it].z); kd[3] = tf32r(kreg[it].w);
                vd[0] = tf32r(vreg[it].x); vd[1] = tf32r(vreg[it].y);
                vd[2] = tf32r(vreg[it].z); vd[3] = tf32r(vreg[it].w);
            }
        }
        __syncthreads();
    }

    // ---- finalize: /l, tf32-round, write [b, s, h*64+d]
    float inv0 = 1.0f / l0r, inv1 = 1.0f / l1r;
    #pragma unroll
    for (int nt = 0; nt < 8; nt++) {
        int col = h * HEAD_DIM + (nt << 3) + (qc << 1);
        size_t r0 = ((size_t)(b * SEQ + q0 + w16 + qr)) * INNER + col;
        size_t r1 = ((size_t)(b * SEQ + q0 + w16 + qr + 8)) * INNER + col;
        *(float2*)&out[r0] = make_float2(tf32r(o[nt][0] * inv0), tf32r(o[nt][1] * inv0));
        *(float2*)&out[r1] = make_float2(tf32r(o[nt][2] * inv1), tf32r(o[nt][3] * inv1));
    }
}

// ---------------------------------------------------------------------------
extern "C" void kernel_launch(void* const* d_in, const int* in_sizes, int n_in,
                              void* d_out, int out_size) {
    const float* x     = (const float*)d_in[0];
    const float* ln_g  = (const float*)d_in[1];
    const float* ln_b  = (const float*)d_in[2];
    const float* w_qkv = (const float*)d_in[3];
    const float* b_qkv = (const float*)d_in[4];
    const float* w_out = (const float*)d_in[5];
    const float* b_out = (const float*)d_in[6];
    float* out = (float*)d_out;

    float *xn, *qkv, *attn, *wq_t, *wo_t;
    cudaGetSymbolAddress((void**)&xn,   g_xn);
    cudaGetSymbolAddress((void**)&qkv,  g_qkv);
    cudaGetSymbolAddress((void**)&attn, g_attn);
    cudaGetSymbolAddress((void**)&wq_t, g_wqkv_t);
    cudaGetSymbolAddress((void**)&wo_t, g_wout_t);

    cudaFuncSetAttribute(attn_kernel, cudaFuncAttributeMaxDynamicSharedMemorySize, ATTN_SMEM);
    cudaFuncSetAttribute(gemm_tf32_kernel, cudaFuncAttributeMaxDynamicSharedMemorySize, GEMM_SMEM);

    // 0) transpose + round weights: W[K][N] -> Wt[N][K] (tf32 RNA)
    transpose_tf32_kernel<<<dim3(3 * INNER / 32, DIM / 32), dim3(32, 8)>>>(
        w_qkv, wq_t, DIM, 3 * INNER);
    transpose_tf32_kernel<<<dim3(DIM / 32, INNER / 32), dim3(32, 8)>>>(
        w_out, wo_t, INNER, DIM);
    // 1) LayerNorm (tf32-rounded output)
    ln_kernel<<<ROWS, 256>>>(x, ln_g, ln_b, xn);
    // 2) QKV projection (tf32 tensor cores, ldmatrix)
    gemm_tf32_kernel<<<dim3((3 * INNER) / 128, ROWS / 128), 256, GEMM_SMEM>>>(
        xn, wq_t, b_qkv, qkv, ROWS, 3 * INNER, DIM);
    // 3) Attention (tensor-core flash, writes [b,s,inner] directly)
    attn_kernel<<<dim3(BATCH * HEADS, SEQ / 128), 256, ATTN_SMEM>>>(qkv, attn);
    // 4) Output projection (tf32 tensor cores, ldmatrix)
    gemm_tf32_kernel<<<dim3(DIM / 128, ROWS / 128), 256, GEMM_SMEM>>>(
        attn, wo_t, b_out, out, ROWS, DIM, INNER);
}

// round 8
// speedup vs baseline: 5.8461x; 1.1252x over previous
#include <cuda_runtime.h>
#include <math.h>
#include <stdint.h>

#define DIM 1024
#define INNER 1024
#define SEQ 2048
#define BATCH 4
#define HEADS 16
#define HEAD_DIM 64
#define ROWS (BATCH*SEQ)            // 8192

// GEMM smem: As[2][128][36] + Bs[2][128][36] floats
#define GEMM_SMEM ((2*128*36 + 2*128*36) * 4)
// attention smem: k[2][64][68] + vt[2][64][68] + p[128][68]
#define ATTN_SMEM ((2*64*68 + 2*64*68 + 128*68) * 4)

// Scratch (no runtime allocation allowed)
__device__ float g_xn[(size_t)ROWS * DIM];
__device__ float g_qkv[(size_t)ROWS * 3 * INNER];
__device__ float g_attn[(size_t)ROWS * INNER];
__device__ float g_vt[(size_t)BATCH * HEADS * HEAD_DIM * SEQ];   // [bh][d][s]
__device__ float g_wqkv_t[(size_t)DIM * 3 * INNER];   // [N=3072][K=1024]
__device__ float g_wout_t[(size_t)INNER * DIM];       // [N=1024][K=1024]

__device__ __forceinline__ float tf32r(float x) {
    uint32_t u;
    asm("cvt.rna.tf32.f32 %0, %1;" : "=r"(u) : "f"(x));
    return __uint_as_float(u);
}

#define MMA_TF32(d0,d1,d2,d3,a0,a1,a2,a3,b0,b1)                              \
    asm volatile(                                                            \
        "mma.sync.aligned.m16n8k8.row.col.f32.tf32.tf32.f32 "                \
        "{%0,%1,%2,%3}, {%4,%5,%6,%7}, {%8,%9}, {%0,%1,%2,%3};"              \
        : "+f"(d0), "+f"(d1), "+f"(d2), "+f"(d3)                             \
        : "r"(a0), "r"(a1), "r"(a2), "r"(a3), "r"(b0), "r"(b1))

__device__ __forceinline__ void ldsm4(uint32_t& r0, uint32_t& r1,
                                      uint32_t& r2, uint32_t& r3, uint32_t a) {
    asm volatile("ldmatrix.sync.aligned.m8n8.x4.shared.b16 {%0,%1,%2,%3}, [%4];"
                 : "=r"(r0), "=r"(r1), "=r"(r2), "=r"(r3) : "r"(a));
}

#define CP_ASYNC16(dst, src) \
    asm volatile("cp.async.cg.shared.global [%0], [%1], 16;" :: "r"(dst), "l"(src))

// ---------------------------------------------------------------------------
// Weight transpose + tf32 round: in[K][N] -> out[N][K]
// ---------------------------------------------------------------------------
__global__ void transpose_tf32_kernel(const float* __restrict__ in, float* __restrict__ out,
                                      int K, int N) {
    __shared__ float tile[32][33];
    int n0 = blockIdx.x << 5, k0 = blockIdx.y << 5;
    int tx = threadIdx.x, ty = threadIdx.y;
    #pragma unroll
    for (int j = 0; j < 4; j++)
        tile[ty + 8 * j][tx] = in[(size_t)(k0 + ty + 8 * j) * N + n0 + tx];
    __syncthreads();
    #pragma unroll
    for (int j = 0; j < 4; j++)
        out[(size_t)(n0 + ty + 8 * j) * K + k0 + tx] = tf32r(tile[tx][ty + 8 * j]);
}

// ---------------------------------------------------------------------------
// V transpose per head: qkv V part [b,s,h,d] -> vt[bh][d][s]
// (values already tf32-rounded by the QKV GEMM epilogue)
// ---------------------------------------------------------------------------
__global__ void transpose_v_kernel(const float* __restrict__ qkv, float* __restrict__ vt) {
    __shared__ float tile[32][33];
    int bh = blockIdx.z;
    int b = bh >> 4, h = bh & 15;
    int s0 = blockIdx.x << 5, d0 = blockIdx.y << 5;
    int tx = threadIdx.x, ty = threadIdx.y;
    #pragma unroll
    for (int j = 0; j < 4; j++)
        tile[ty + 8 * j][tx] =
            qkv[(size_t)(b * SEQ + s0 + ty + 8 * j) * 3072 + 2 * INNER + h * HEAD_DIM + d0 + tx];
    __syncthreads();
    #pragma unroll
    for (int j = 0; j < 4; j++)
        vt[(size_t)(bh * HEAD_DIM + d0 + ty + 8 * j) * SEQ + s0 + tx] = tile[tx][ty + 8 * j];
}

// ---------------------------------------------------------------------------
// LayerNorm: one block per row of 1024, 256 threads, tf32-rounded output
// ---------------------------------------------------------------------------
__global__ void ln_kernel(const float* __restrict__ x, const float* __restrict__ g,
                          const float* __restrict__ beta, float* __restrict__ out) {
    int row = blockIdx.x;
    int t = threadIdx.x;
    const float4* xr = (const float4*)(x + (size_t)row * DIM);
    float4 v = xr[t];
    float s  = v.x + v.y + v.z + v.w;
    float ss = v.x*v.x + v.y*v.y + v.z*v.z + v.w*v.w;
    #pragma unroll
    for (int o = 16; o; o >>= 1) {
        s  += __shfl_xor_sync(0xffffffffu, s,  o);
        ss += __shfl_xor_sync(0xffffffffu, ss, o);
    }
    __shared__ float sbuf[8], ssbuf[8];
    __shared__ float mu_s, rstd_s;
    if ((t & 31) == 0) { sbuf[t >> 5] = s; ssbuf[t >> 5] = ss; }
    __syncthreads();
    if (t == 0) {
        float st = 0.f, sst = 0.f;
        #pragma unroll
        for (int i = 0; i < 8; i++) { st += sbuf[i]; sst += ssbuf[i]; }
        float mu  = st * (1.0f / DIM);
        float var = sst * (1.0f / DIM) - mu * mu;
        mu_s = mu;
        rstd_s = rsqrtf(var + 1e-5f);
    }
    __syncthreads();
    float mu = mu_s, rstd = rstd_s;
    float4 gv = ((const float4*)g)[t];
    float4 bv = ((const float4*)beta)[t];
    float4 o4;
    o4.x = tf32r((v.x - mu) * rstd * gv.x + bv.x);
    o4.y = tf32r((v.y - mu) * rstd * gv.y + bv.y);
    o4.z = tf32r((v.z - mu) * rstd * gv.z + bv.z);
    o4.w = tf32r((v.w - mu) * rstd * gv.w + bv.w);
    ((float4*)(out + (size_t)row * DIM))[t] = o4;
}

// ---------------------------------------------------------------------------
// tf32 tensor-core GEMM + bias: C[M,N] = A[M,K] @ Bt[N,K]^T + bias[N]
// ROUND_OUT: tf32-round the stored C (used for qkv, consumed by tf32 mma later)
// ---------------------------------------------------------------------------
template <bool ROUND_OUT>
__global__ __launch_bounds__(256, 2)
void gemm_tf32_kernel(const float* __restrict__ A, const float* __restrict__ Bt,
                      const float* __restrict__ bias, float* __restrict__ C,
                      int M, int N, int K) {
    extern __shared__ float sm[];
    float* As = sm;                       // [2][128][36]
    float* Bs = sm + 2 * 128 * 36;        // [2][128][36]

    int t = threadIdx.x;
    int warp = t >> 5, lane = t & 31;
    int warp_m = warp >> 2;               // 0..1
    int warp_n = warp & 3;                // 0..3
    int qr = lane >> 2;                   // 0..7
    int qc = lane & 3;                    // 0..3
    int m0 = blockIdx.y << 7;
    int n0 = blockIdx.x << 7;
    int mb = warp_m << 6;
    int nb = warp_n << 5;

    uint32_t as_base = (uint32_t)__cvta_generic_to_shared(As);
    uint32_t bs_base = (uint32_t)__cvta_generic_to_shared(Bs);

    int lr8 = lane & 7;
    int aoff = (mb + (((lane >> 3) & 1) << 3) + lr8) * 36 + ((lane >> 4) << 2);
    int boff = (nb + ((lane >> 4) << 3) + lr8) * 36 + (((lane >> 3) & 1) << 2);

    float acc[4][4][4] = {};

    {
        #pragma unroll
        for (int j = 0; j < 4; j++) {
            int idx = t + (j << 8);
            int r = idx >> 3, kc = (idx & 7) << 2;
            CP_ASYNC16(as_base + (uint32_t)(r * 36 + kc) * 4,
                       A + (size_t)(m0 + r) * K + kc);
            CP_ASYNC16(bs_base + (uint32_t)(r * 36 + kc) * 4,
                       Bt + (size_t)(n0 + r) * K + kc);
        }
        asm volatile("cp.async.commit_group;");
    }

    int nk = K >> 5;
    for (int k0 = 0; k0 < nk; k0++) {
        asm volatile("cp.async.wait_group 0;");
        __syncthreads();
        int cur = k0 & 1;
        if (k0 + 1 < nk) {
            int nxt = cur ^ 1;
            int kbase = (k0 + 1) << 5;
            uint32_t asn = as_base + (uint32_t)(nxt * 128 * 36) * 4;
            uint32_t bsn = bs_base + (uint32_t)(nxt * 128 * 36) * 4;
            #pragma unroll
            for (int j = 0; j < 4; j++) {
                int idx = t + (j << 8);
                int r = idx >> 3, kc = (idx & 7) << 2;
                CP_ASYNC16(asn + (uint32_t)(r * 36 + kc) * 4,
                           A + (size_t)(m0 + r) * K + kbase + kc);
                CP_ASYNC16(bsn + (uint32_t)(r * 36 + kc) * 4,
                           Bt + (size_t)(n0 + r) * K + kbase + kc);
            }
            asm volatile("cp.async.commit_group;");
        }

        uint32_t ac = as_base + (uint32_t)(cur * 128 * 36) * 4;
        uint32_t bc = bs_base + (uint32_t)(cur * 128 * 36) * 4;

        #pragma unroll
        for (int ks = 0; ks < 4; ks++) {
            int k8 = ks << 3;
            uint32_t af[4][4], bf[4][2];
            #pragma unroll
            for (int mt = 0; mt < 4; mt++)
                ldsm4(af[mt][0], af[mt][1], af[mt][2], af[mt][3],
                      ac + (uint32_t)(aoff + mt * 16 * 36 + k8) * 4);
            #pragma unroll
            for (int ntp = 0; ntp < 2; ntp++)
                ldsm4(bf[2*ntp][0], bf[2*ntp][1], bf[2*ntp+1][0], bf[2*ntp+1][1],
                      bc + (uint32_t)(boff + ntp * 16 * 36 + k8) * 4);
            #pragma unroll
            for (int mt = 0; mt < 4; mt++)
                #pragma unroll
                for (int nt = 0; nt < 4; nt++)
                    MMA_TF32(acc[mt][nt][0], acc[mt][nt][1], acc[mt][nt][2], acc[mt][nt][3],
                             af[mt][0], af[mt][1], af[mt][2], af[mt][3],
                             bf[nt][0], bf[nt][1]);
        }
        __syncthreads();
    }

    #pragma unroll
    for (int nt = 0; nt < 4; nt++) {
        int col = n0 + nb + (nt << 3) + (qc << 1);
        float2 bb = *(const float2*)&bias[col];
        #pragma unroll
        for (int mt = 0; mt < 4; mt++) {
            int row = m0 + mb + (mt << 4) + qr;
            float2 v0, v1;
            if (ROUND_OUT) {
                v0 = make_float2(tf32r(acc[mt][nt][0] + bb.x), tf32r(acc[mt][nt][1] + bb.y));
                v1 = make_float2(tf32r(acc[mt][nt][2] + bb.x), tf32r(acc[mt][nt][3] + bb.y));
            } else {
                v0 = make_float2(acc[mt][nt][0] + bb.x, acc[mt][nt][1] + bb.y);
                v1 = make_float2(acc[mt][nt][2] + bb.x, acc[mt][nt][3] + bb.y);
            }
            *(float2*)&C[(size_t)row * N + col] = v0;
            *(float2*)&C[(size_t)(row + 8) * N + col] = v1;
        }
    }
}

// ---------------------------------------------------------------------------
// Tensor-core flash attention, fully ldmatrix/cp.async.
// grid (b*h=64, qtile=16), 256 threads (8 warps), 128q x 64kv tile.
// K [kv][d] and Vt [d][kv] tiles via cp.async (pre-rounded tf32 values).
// S frags: Q(A,reg) x K(B,ldsm). PV frags: P(A,ldsm) x Vt(B,ldsm).
// ---------------------------------------------------------------------------
#define KSTR 68
#define PSTR 68

__global__ __launch_bounds__(256, 2)
void attn_kernel(const float* __restrict__ qkv, const float* __restrict__ vt,
                 float* __restrict__ out) {
    extern __shared__ float sh[];
    float* k_s  = sh;                     // [2][64][KSTR]
    float* vt_s = k_s + 2 * 64 * KSTR;    // [2][64][KSTR]
    float* p_s  = vt_s + 2 * 64 * KSTR;   // [128][PSTR]

    int b  = blockIdx.x >> 4;
    int h  = blockIdx.x & 15;
    int bh = blockIdx.x;
    int q0 = blockIdx.y << 7;
    int t  = threadIdx.x;
    int warp = t >> 5, lane = t & 31;
    int qr = lane >> 2, qc = lane & 3;
    int w16 = warp << 4;
    int lr8 = lane & 7;

    uint32_t ks_base = (uint32_t)__cvta_generic_to_shared(k_s);
    uint32_t vs_base = (uint32_t)__cvta_generic_to_shared(vt_s);
    uint32_t ps_base = (uint32_t)__cvta_generic_to_shared(p_s);

    // loader mapping: 4 rows of 16B per thread per tile (per operand)
    int lr = t >> 4;                 // 0..15 (+16 per it)
    int lc = (t & 15) << 2;          // 0..60

    // ---- prologue: issue cp.async for KV tile 0
    #pragma unroll
    for (int it = 0; it < 4; it++) {
        int r = lr + (it << 4);
        CP_ASYNC16(ks_base + (uint32_t)(r * KSTR + lc) * 4,
                   qkv + (size_t)(b * SEQ + r) * 3072 + INNER + h * HEAD_DIM + lc);
        CP_ASYNC16(vs_base + (uint32_t)(r * KSTR + lc) * 4,
                   vt + (size_t)(bh * HEAD_DIM + r) * SEQ + lc);
    }
    asm volatile("cp.async.commit_group;");

    // ---- Stage Q (x0.125, exact in tf32; values pre-rounded by QKV GEMM)
    #pragma unroll
    for (int it = 0; it < 8; it++) {
        int idx = t + (it << 8);
        int r = idx >> 4, c = (idx & 15) << 2;
        size_t g = ((size_t)(b * SEQ + q0 + r)) * 3072 + h * HEAD_DIM + c;
        float4 v = *(const float4*)(qkv + g);
        *(float4*)&p_s[r * PSTR + c] =
            make_float4(v.x * 0.125f, v.y * 0.125f, v.z * 0.125f, v.w * 0.125f);
    }
    __syncthreads();

    // A-pattern ldmatrix offsets (rows +8 on bit3, cols +4 on bit4)
    int qoff = (w16 + (((lane >> 3) & 1) << 3) + lr8) * PSTR + ((lane >> 4) << 2);
    uint32_t qf[8][4];
    #pragma unroll
    for (int ks = 0; ks < 8; ks++)
        ldsm4(qf[ks][0], qf[ks][1], qf[ks][2], qf[ks][3],
              ps_base + (uint32_t)(qoff + (ks << 3)) * 4);
    // (no sync needed: each warp's P rows are warp-private from here on)

    // B-pattern ldmatrix offsets (cols +4 on bit3, rows +8 on bit4)
    int boff = (((lane >> 4) << 3) + lr8) * KSTR + (((lane >> 3) & 1) << 2);

    float o[8][4] = {};
    float m0r = -1e30f, m1r = -1e30f, l0r = 0.f, l1r = 0.f;

    for (int kt = 0; kt < SEQ / 64; kt++) {
        int cur = kt & 1;
        asm volatile("cp.async.wait_group 0;");
        __syncthreads();

        // issue next tile into the other buffer
        if (kt + 1 < SEQ / 64) {
            int nxt = cur ^ 1;
            uint32_t kb = ks_base + (uint32_t)(nxt * 64 * KSTR) * 4;
            uint32_t vb = vs_base + (uint32_t)(nxt * 64 * KSTR) * 4;
            int s1 = (kt + 1) << 6;
            #pragma unroll
            for (int it = 0; it < 4; it++) {
                int r = lr + (it << 4);
                CP_ASYNC16(kb + (uint32_t)(r * KSTR + lc) * 4,
                           qkv + (size_t)(b * SEQ + s1 + r) * 3072 + INNER + h * HEAD_DIM + lc);
                CP_ASYNC16(vb + (uint32_t)(r * KSTR + lc) * 4,
                           vt + (size_t)(bh * HEAD_DIM + r) * SEQ + s1 + lc);
            }
            asm volatile("cp.async.commit_group;");
        }

        uint32_t kc_b = ks_base + (uint32_t)(cur * 64 * KSTR) * 4;
        uint32_t vc_b = vs_base + (uint32_t)(cur * 64 * KSTR) * 4;

        // ---- S = Q K^T : per warp 16x64
        float s[8][4] = {};
        #pragma unroll
        for (int ks = 0; ks < 8; ks++) {
            int k8 = ks << 3;
            #pragma unroll
            for (int ntp = 0; ntp < 4; ntp++) {
                uint32_t b00, b01, b10, b11;
                ldsm4(b00, b01, b10, b11,
                      kc_b + (uint32_t)(boff + ntp * 16 * KSTR + k8) * 4);
                MMA_TF32(s[2*ntp][0], s[2*ntp][1], s[2*ntp][2], s[2*ntp][3],
                         qf[ks][0], qf[ks][1], qf[ks][2], qf[ks][3], b00, b01);
                MMA_TF32(s[2*ntp+1][0], s[2*ntp+1][1], s[2*ntp+1][2], s[2*ntp+1][3],
                         qf[ks][0], qf[ks][1], qf[ks][2], qf[ks][3], b10, b11);
            }
        }

        // ---- online softmax (rows qr, qr+8; reduce over 4 qc lanes)
        float mt0 = -1e30f, mt1 = -1e30f;
        #pragma unroll
        for (int nt = 0; nt < 8; nt++) {
            mt0 = fmaxf(mt0, fmaxf(s[nt][0], s[nt][1]));
            mt1 = fmaxf(mt1, fmaxf(s[nt][2], s[nt][3]));
        }
        mt0 = fmaxf(mt0, __shfl_xor_sync(0xffffffffu, mt0, 1));
        mt0 = fmaxf(mt0, __shfl_xor_sync(0xffffffffu, mt0, 2));
        mt1 = fmaxf(mt1, __shfl_xor_sync(0xffffffffu, mt1, 1));
        mt1 = fmaxf(mt1, __shfl_xor_sync(0xffffffffu, mt1, 2));
        float mn0 = fmaxf(m0r, mt0), mn1 = fmaxf(m1r, mt1);
        float corr0 = __expf(m0r - mn0), corr1 = __expf(m1r - mn1);
        float ls0 = 0.f, ls1 = 0.f;
        #pragma unroll
        for (int nt = 0; nt < 8; nt++) {
            s[nt][0] = __expf(s[nt][0] - mn0); ls0 += s[nt][0];
            s[nt][1] = __expf(s[nt][1] - mn0); ls0 += s[nt][1];
            s[nt][2] = __expf(s[nt][2] - mn1); ls1 += s[nt][2];
            s[nt][3] = __expf(s[nt][3] - mn1); ls1 += s[nt][3];
        }
        ls0 += __shfl_xor_sync(0xffffffffu, ls0, 1);
        ls0 += __shfl_xor_sync(0xffffffffu, ls0, 2);
        ls1 += __shfl_xor_sync(0xffffffffu, ls1, 1);
        ls1 += __shfl_xor_sync(0xffffffffu, ls1, 2);
        l0r = l0r * corr0 + ls0;  m0r = mn0;
        l1r = l1r * corr1 + ls1;  m1r = mn1;
        #pragma unroll
        for (int nt = 0; nt < 8; nt++) {
            o[nt][0] *= corr0; o[nt][1] *= corr0;
            o[nt][2] *= corr1; o[nt][3] *= corr1;
        }

        // ---- write P (tf32) to warp-private p_s rows
        #pragma unroll
        for (int nt = 0; nt < 8; nt++) {
            int colp = (nt << 3) + (qc << 1);
            *(float2*)&p_s[(w16 + qr) * PSTR + colp] =
                make_float2(tf32r(s[nt][0]), tf32r(s[nt][1]));
            *(float2*)&p_s[(w16 + qr + 8) * PSTR + colp] =
                make_float2(tf32r(s[nt][2]), tf32r(s[nt][3]));
        }
        __syncwarp();

        // ---- O += P Vt^T : per warp 16x64, both operands via ldmatrix
        #pragma unroll
        for (int ks = 0; ks < 8; ks++) {
            int k8 = ks << 3;
            uint32_t a0, a1, a2, a3;
            ldsm4(a0, a1, a2, a3, ps_base + (uint32_t)(qoff + k8) * 4);
            #pragma unroll
            for (int ntp = 0; ntp < 4; ntp++) {
                uint32_t b00, b01, b10, b11;
                ldsm4(b00, b01, b10, b11,
                      vc_b + (uint32_t)(boff + ntp * 16 * KSTR + k8) * 4);
                MMA_TF32(o[2*ntp][0], o[2*ntp][1], o[2*ntp][2], o[2*ntp][3],
                         a0, a1, a2, a3, b00, b01);
                MMA_TF32(o[2*ntp+1][0], o[2*ntp+1][1], o[2*ntp+1][2], o[2*ntp+1][3],
                         a0, a1, a2, a3, b10, b11);
            }
        }
    }

    // ---- finalize: /l, tf32-round, write [b, s, h*64+d]
    float inv0 = 1.0f / l0r, inv1 = 1.0f / l1r;
    #pragma unroll
    for (int nt = 0; nt < 8; nt++) {
        int col = h * HEAD_DIM + (nt << 3) + (qc << 1);
        size_t r0 = ((size_t)(b * SEQ + q0 + w16 + qr)) * INNER + col;
        size_t r1 = ((size_t)(b * SEQ + q0 + w16 + qr + 8)) * INNER + col;
        *(float2*)&out[r0] = make_float2(tf32r(o[nt][0] * inv0), tf32r(o[nt][1] * inv0));
        *(float2*)&out[r1] = make_float2(tf32r(o[nt][2] * inv1), tf32r(o[nt][3] * inv1));
    }
}

// ---------------------------------------------------------------------------
extern "C" void kernel_launch(void* const* d_in, const int* in_sizes, int n_in,
                              void* d_out, int out_size) {
    const float* x     = (const float*)d_in[0];
    const float* ln_g  = (const float*)d_in[1];
    const float* ln_b  = (const float*)d_in[2];
    const float* w_qkv = (const float*)d_in[3];
    const float* b_qkv = (const float*)d_in[4];
    const float* w_out = (const float*)d_in[5];
    const float* b_out = (const float*)d_in[6];
    float* out = (float*)d_out;

    float *xn, *qkv, *attn, *vtp, *wq_t, *wo_t;
    cudaGetSymbolAddress((void**)&xn,   g_xn);
    cudaGetSymbolAddress((void**)&qkv,  g_qkv);
    cudaGetSymbolAddress((void**)&attn, g_attn);
    cudaGetSymbolAddress((void**)&vtp,  g_vt);
    cudaGetSymbolAddress((void**)&wq_t, g_wqkv_t);
    cudaGetSymbolAddress((void**)&wo_t, g_wout_t);

    cudaFuncSetAttribute(attn_kernel, cudaFuncAttributeMaxDynamicSharedMemorySize, ATTN_SMEM);
    cudaFuncSetAttribute(gemm_tf32_kernel<true>,
                         cudaFuncAttributeMaxDynamicSharedMemorySize, GEMM_SMEM);
    cudaFuncSetAttribute(gemm_tf32_kernel<false>,
                         cudaFuncAttributeMaxDynamicSharedMemorySize, GEMM_SMEM);

    // 0) transpose + round weights: W[K][N] -> Wt[N][K] (tf32 RNA)
    transpose_tf32_kernel<<<dim3(3 * INNER / 32, DIM / 32), dim3(32, 8)>>>(
        w_qkv, wq_t, DIM, 3 * INNER);
    transpose_tf32_kernel<<<dim3(DIM / 32, INNER / 32), dim3(32, 8)>>>(
        w_out, wo_t, INNER, DIM);
    // 1) LayerNorm (tf32-rounded output)
    ln_kernel<<<ROWS, 256>>>(x, ln_g, ln_b, xn);
    // 2) QKV projection (tf32 tensor cores; output tf32-rounded)
    gemm_tf32_kernel<true><<<dim3((3 * INNER) / 128, ROWS / 128), 256, GEMM_SMEM>>>(
        xn, wq_t, b_qkv, qkv, ROWS, 3 * INNER, DIM);
    // 2b) per-head V transpose -> vt[bh][d][s]
    transpose_v_kernel<<<dim3(SEQ / 32, HEAD_DIM / 32, BATCH * HEADS), dim3(32, 8)>>>(qkv, vtp);
    // 3) Attention (tensor-core flash, writes [b,s,inner] directly)
    attn_kernel<<<dim3(BATCH * HEADS, SEQ / 128), 256, ATTN_SMEM>>>(qkv, vtp, attn);
    // 4) Output projection (tf32 tensor cores, fp32 output)
    gemm_tf32_kernel<false><<<dim3(DIM / 128, ROWS / 128), 256, GEMM_SMEM>>>(
        attn, wo_t, b_out, out, ROWS, DIM, INNER);
}